// round 7
// baseline (speedup 1.0000x reference)
#include <cuda_runtime.h>
#include <cuda_bf16.h>
#include <math.h>
#include <stdint.h>

#define B_ 8
#define T_ 64
#define N_ 256
#define H_ 8
#define D_ 64
#define FEAT 512
#define TOKENS (B_*T_*N_)          /* 131072 */
#define ELEMS  (TOKENS*FEAT)       /* 67108864 */
#define WSZ    (512*512)

// ---------------------------------------------------------------------------
// Scratch (device globals — no cudaMalloc allowed)
// ---------------------------------------------------------------------------
__device__ float g_s2[ELEMS];   // q, later ff2
__device__ float g_s3[ELEMS];   // k, later o (Wo out)
__device__ float g_s4[ELEMS];   // v, later val
__device__ __nv_bfloat16 g_bf[10ull * ELEMS];
__device__ __nv_bfloat16 g_wh[6 * WSZ];
__device__ __nv_bfloat16 g_wl[6 * WSZ];

// ---------------------------------------------------------------------------
// Helpers
// ---------------------------------------------------------------------------
__device__ __forceinline__ uint32_t smem_u32(const void* p) {
    uint32_t a;
    asm("{ .reg .u64 t; cvta.to.shared.u64 t, %1; cvt.u32.u64 %0, t; }" : "=r"(a) : "l"(p));
    return a;
}

__device__ __forceinline__ void cp16(uint32_t dst, const void* src) {
    asm volatile("cp.async.cg.shared.global [%0], [%1], 16;"
                 :: "r"(dst), "l"(__cvta_generic_to_global(src)));
}

__device__ __forceinline__ void ldsm4(uint32_t addr, uint32_t* r) {
    asm volatile("ldmatrix.sync.aligned.m8n8.x4.shared.b16 {%0,%1,%2,%3}, [%4];"
                 : "=r"(r[0]), "=r"(r[1]), "=r"(r[2]), "=r"(r[3]) : "r"(addr));
}

__device__ __forceinline__ void mma_bf16(float* d, const uint32_t* a,
                                         uint32_t b0, uint32_t b1) {
    asm volatile(
        "mma.sync.aligned.m16n8k16.row.col.f32.bf16.bf16.f32 "
        "{%0,%1,%2,%3}, {%4,%5,%6,%7}, {%8,%9}, {%0,%1,%2,%3};"
        : "+f"(d[0]), "+f"(d[1]), "+f"(d[2]), "+f"(d[3])
        : "r"(a[0]), "r"(a[1]), "r"(a[2]), "r"(a[3]), "r"(b0), "r"(b1));
}

__device__ __forceinline__ void split2(float x, float y,
                                       __nv_bfloat162& h, __nv_bfloat162& l) {
    h = __floats2bfloat162_rn(x, y);
    l = __floats2bfloat162_rn(x - __low2float(h), y - __high2float(h));
}

// ---------------------------------------------------------------------------
// Weight prep: transpose + hi/lo split. Wh/Wl[z][n][k] = split(W_z[k][n]).
// ---------------------------------------------------------------------------
__global__ __launch_bounds__(256)
void prep_w(const float* W0, const float* W1, const float* W2,
            const float* W3, const float* W4, const float* W5,
            __nv_bfloat16* __restrict__ Wh, __nv_bfloat16* __restrict__ Wl)
{
    const float* Ws[6] = {W0, W1, W2, W3, W4, W5};
    const float* W = Ws[blockIdx.z];
    __shared__ float t[32][33];
    int bx = blockIdx.x * 32, by = blockIdx.y * 32;
#pragma unroll
    for (int r = 0; r < 32; r += 8)
        t[threadIdx.y + r][threadIdx.x] =
            W[(size_t)(by + threadIdx.y + r) * 512 + bx + threadIdx.x];
    __syncthreads();
    size_t base = (size_t)blockIdx.z * WSZ;
#pragma unroll
    for (int r = 0; r < 32; r += 8) {
        float v = t[threadIdx.x][threadIdx.y + r];
        __nv_bfloat16 h = __float2bfloat16_rn(v);
        size_t o = base + (size_t)(bx + threadIdx.y + r) * 512 + by + threadIdx.x;
        Wh[o] = h;
        Wl[o] = __float2bfloat16_rn(v - __bfloat162float(h));
    }
}

// ---------------------------------------------------------------------------
// Fused residual adds: split(xl+te) -> s0h/l (no fp32 copy), split(xh+te).
// ---------------------------------------------------------------------------
__global__ __launch_bounds__(256)
void add_te01(const float4* __restrict__ xl, const float4* __restrict__ xh,
              const float4* __restrict__ te,
              __nv_bfloat162* __restrict__ h0o, __nv_bfloat162* __restrict__ l0o,
              __nv_bfloat162* __restrict__ h1o, __nv_bfloat162* __restrict__ l1o)
{
    int i = blockIdx.x * 256 + threadIdx.x;
    float4 t = te[i];
    float4 a = xl[i];
    float4 b = xh[i];
    float4 r0 = make_float4(a.x + t.x, a.y + t.y, a.z + t.z, a.w + t.w);
    float4 r1 = make_float4(b.x + t.x, b.y + t.y, b.z + t.z, b.w + t.w);
    __nv_bfloat162 h0, l0, h1, l1;
    split2(r0.x, r0.y, h0, l0);
    split2(r0.z, r0.w, h1, l1);
    h0o[2 * i] = h0; h0o[2 * i + 1] = h1;
    l0o[2 * i] = l0; l0o[2 * i + 1] = l1;
    split2(r1.x, r1.y, h0, l0);
    split2(r1.z, r1.w, h1, l1);
    h1o[2 * i] = h0; h1o[2 * i + 1] = h1;
    l1o[2 * i] = l0; l1o[2 * i + 1] = l1;
}

// ---------------------------------------------------------------------------
// 3xBF16 tensor-core GEMM, 2-stage cp.async pipeline.
// CTA 128x128, 256 threads, 8 warps (32x64 warp tiles) — spill-free.
// Dual-B: blocks with blockIdx.x>=4 use second operand set (fused K+V).
// ---------------------------------------------------------------------------
__global__ __launch_bounds__(256, 2)
void gemm_bf3(const __nv_bfloat16* __restrict__ Ah, const __nv_bfloat16* __restrict__ Al,
              const __nv_bfloat16* __restrict__ Bh, const __nv_bfloat16* __restrict__ Bl,
              const float* __restrict__ bias,
              float* __restrict__ Cf,
              __nv_bfloat16* __restrict__ Ch, __nv_bfloat16* __restrict__ Cl,
              int relu,
              const __nv_bfloat16* Bh2, const __nv_bfloat16* Bl2,
              const float* bias2, float* Cf2, int relu2)
{
    extern __shared__ __align__(128) unsigned char smem[];
    const uint32_t sb = smem_u32(smem);

    const int tid  = threadIdx.x;
    const int lane = tid & 31;
    const int warp = tid >> 5;
    const int wm = warp >> 1, wn = warp & 1;   // 4 x 2 warp grid
    const int m0 = blockIdx.y * 128;

    int bx = blockIdx.x;
    const __nv_bfloat16* BhU = Bh;
    const __nv_bfloat16* BlU = Bl;
    const float* biasU = bias;
    float* CfU = Cf;
    int reluU = relu;
    if (bx >= 4) {
        bx -= 4;
        BhU = Bh2; BlU = Bl2; biasU = bias2; CfU = Cf2; reluU = relu2;
    }
    const int n0 = bx * 128;

    const __nv_bfloat16* Ahg = Ah  + (size_t)m0 * 512;
    const __nv_bfloat16* Alg = Al  + (size_t)m0 * 512;
    const __nv_bfloat16* Bhg = BhU + (size_t)n0 * 512;
    const __nv_bfloat16* Blg = BlU + (size_t)n0 * 512;

    int frow[2], fc[2];
    uint32_t foff[2];
#pragma unroll
    for (int j = 0; j < 2; j++) {
        int lin = tid + j * 256;
        frow[j] = lin >> 2;
        fc[j]   = lin & 3;
        foff[j] = frow[j] * 64 + ((uint32_t)(fc[j] ^ ((frow[j] >> 1) & 3)) << 4);
    }

#define FILL(kc, st)                                                          \
    do {                                                                      \
        uint32_t s_ = sb + (st) * 32768;                                      \
        _Pragma("unroll")                                                     \
        for (int j = 0; j < 2; j++) {                                         \
            size_t g_ = (size_t)frow[j] * 512 + (kc) * 32 + fc[j] * 8;        \
            cp16(s_ + foff[j],          Ahg + g_);                            \
            cp16(s_ + 8192  + foff[j],  Alg + g_);                            \
            cp16(s_ + 16384 + foff[j],  Bhg + g_);                            \
            cp16(s_ + 24576 + foff[j],  Blg + g_);                            \
        }                                                                     \
        asm volatile("cp.async.commit_group;");                               \
    } while (0)

    float acc[2][8][4];
#pragma unroll
    for (int i = 0; i < 2; i++)
#pragma unroll
        for (int j = 0; j < 8; j++)
#pragma unroll
            for (int k = 0; k < 4; k++) acc[i][j][k] = 0.f;

    const int rA_base = wm * 32 + (lane & 7) + ((lane >> 3) & 1) * 8;
    const uint32_t kbA = ((lane >> 4) & 1) * 16;
    const int rB_base = wn * 64 + (lane & 7) + ((lane >> 4) & 1) * 8;
    const uint32_t kbB = ((lane >> 3) & 1) * 16;

    FILL(0, 0);
    FILL(1, 1);

    for (int c = 0; c < 16; c++) {
        if (c < 15) asm volatile("cp.async.wait_group 1;");
        else        asm volatile("cp.async.wait_group 0;");
        __syncthreads();

        const uint32_t st = (c & 1) * 32768;
        const uint32_t sAh = sb + st, sAl = sAh + 8192;
        const uint32_t sBh = sAh + 16384, sBl = sAh + 24576;

#pragma unroll
        for (int ks = 0; ks < 2; ks++) {
            uint32_t ah[2][4], al[2][4];
#pragma unroll
            for (int mt = 0; mt < 2; mt++) {
                int r = rA_base + mt * 16;
                uint32_t kb = kbA + ks * 32;
                uint32_t off = r * 64 + (kb ^ (((r >> 1) & 3) << 4));
                ldsm4(sAh + off, ah[mt]);
                ldsm4(sAl + off, al[mt]);
            }
#pragma unroll
            for (int p = 0; p < 4; p++) {
                uint32_t bh[4], bl[4];
                int r = rB_base + p * 16;
                uint32_t kb = kbB + ks * 32;
                uint32_t off = r * 64 + (kb ^ (((r >> 1) & 3) << 4));
                ldsm4(sBh + off, bh);
                ldsm4(sBl + off, bl);
#pragma unroll
                for (int mt = 0; mt < 2; mt++) {
                    mma_bf16(acc[mt][2 * p],     ah[mt], bh[0], bh[1]);
                    mma_bf16(acc[mt][2 * p],     ah[mt], bl[0], bl[1]);
                    mma_bf16(acc[mt][2 * p],     al[mt], bh[0], bh[1]);
                    mma_bf16(acc[mt][2 * p + 1], ah[mt], bh[2], bh[3]);
                    mma_bf16(acc[mt][2 * p + 1], ah[mt], bl[2], bl[3]);
                    mma_bf16(acc[mt][2 * p + 1], al[mt], bh[2], bh[3]);
                }
            }
        }
        __syncthreads();
        if (c + 2 < 16) FILL(c + 2, (c & 1));
    }

    // ---- epilogue ----
#pragma unroll
    for (int mt = 0; mt < 2; mt++) {
        int row = m0 + wm * 32 + mt * 16 + (lane >> 2);
#pragma unroll
        for (int nt = 0; nt < 8; nt++) {
            int col = n0 + wn * 64 + nt * 8 + (lane & 3) * 2;
            float2 bb = __ldg((const float2*)(biasU + col));
            float v0 = acc[mt][nt][0] + bb.x;
            float v1 = acc[mt][nt][1] + bb.y;
            float v2 = acc[mt][nt][2] + bb.x;
            float v3 = acc[mt][nt][3] + bb.y;
            if (reluU) {
                v0 = fmaxf(v0, 0.f); v1 = fmaxf(v1, 0.f);
                v2 = fmaxf(v2, 0.f); v3 = fmaxf(v3, 0.f);
            }
            if (CfU) {
                *(float2*)(CfU + (size_t)row * 512 + col)       = make_float2(v0, v1);
                *(float2*)(CfU + (size_t)(row + 8) * 512 + col) = make_float2(v2, v3);
            }
            if (Ch) {
                __nv_bfloat162 h0, l0, h1, l1;
                split2(v0, v1, h0, l0);
                split2(v2, v3, h1, l1);
                *(__nv_bfloat162*)(Ch + (size_t)row * 512 + col)       = h0;
                *(__nv_bfloat162*)(Cl + (size_t)row * 512 + col)       = l0;
                *(__nv_bfloat162*)(Ch + (size_t)(row + 8) * 512 + col) = h1;
                *(__nv_bfloat162*)(Cl + (size_t)(row + 8) * 512 + col) = l1;
            }
        }
    }
#undef FILL
}

// ---------------------------------------------------------------------------
// Causal attention per (b, n, h): T=64, D=64. Register-blocked (R6 WIN).
// Masked BEFORE scaling: masked logit = -32767/8.
// ---------------------------------------------------------------------------
__global__ __launch_bounds__(256)
void attn64(const float* __restrict__ q, const float* __restrict__ k,
            const float* __restrict__ v,
            __nv_bfloat16* __restrict__ oh, __nv_bfloat16* __restrict__ ol)
{
    __shared__ float Qs[64 * 64];   // Q, then P (per-warp rows)
    __shared__ float Ks[64 * 64];   // chunk-swizzled
    __shared__ float Vs[64 * 64];   // float2-interleaved

    const int idx = blockIdx.x;
    const int h = idx & 7;
    const int n = (idx >> 3) & 255;
    const int b = idx >> 11;
    const size_t base = ((size_t)(b * T_) * N_ + n) * FEAT + h * D_;
    const int tid = threadIdx.x;
    const size_t tstride = (size_t)N_ * FEAT;

    for (int i = tid; i < 4096; i += 256) {
        int t = i >> 6, d = i & 63;
        size_t off = base + (size_t)t * tstride + d;
        Qs[i] = q[off];
        Ks[t * 64 + ((((d >> 2) ^ (t & 7)) << 2) | (d & 3))] = k[off];
        Vs[t * 64 + ((d & 31) * 2 + (d >> 5))] = v[off];
    }
    __syncthreads();

    const int w = tid >> 5;
    const int l = tid & 31;
    const float NEG8 = -4095.875f;
    const float4* Kf4 = (const float4*)Ks;
    const float4* Qf4 = (const float4*)Qs;
    const int csw = l & 7;

    float s0[8], s1[8];
#pragma unroll
    for (int r = 0; r < 8; r++) { s0[r] = 0.f; s1[r] = 0.f; }
#pragma unroll
    for (int c = 0; c < 16; c++) {
        float4 k0 = Kf4[l * 16 + (c ^ csw)];
        float4 k1 = Kf4[(l + 32) * 16 + (c ^ csw)];
#pragma unroll
        for (int r = 0; r < 8; r++) {
            float4 q4 = Qf4[(w * 8 + r) * 16 + c];
            s0[r] += q4.x * k0.x + q4.y * k0.y + q4.z * k0.z + q4.w * k0.w;
            s1[r] += q4.x * k1.x + q4.y * k1.y + q4.z * k1.z + q4.w * k1.w;
        }
    }

#pragma unroll
    for (int r = 0; r < 8; r++) {
        int t = w * 8 + r;
        float l0 = (l      <= t) ? s0[r] * 0.125f : NEG8;
        float l1 = (l + 32 <= t) ? s1[r] * 0.125f : NEG8;
        float m = fmaxf(l0, l1);
#pragma unroll
        for (int o = 16; o; o >>= 1) m = fmaxf(m, __shfl_xor_sync(0xffffffffu, m, o));
        float e0 = __expf(l0 - m), e1 = __expf(l1 - m);
        float sum = e0 + e1;
#pragma unroll
        for (int o = 16; o; o >>= 1) sum += __shfl_xor_sync(0xffffffffu, sum, o);
        float inv = 1.f / sum;
        s0[r] = e0 * inv;
        s1[r] = e1 * inv;
    }

    __syncwarp();
#pragma unroll
    for (int r = 0; r < 8; r++) {
        int t = w * 8 + r;
        Qs[t * 64 + l]      = s0[r];
        Qs[t * 64 + l + 32] = s1[r];
    }
    __syncwarp();

    float a0[8], a1[8];
#pragma unroll
    for (int r = 0; r < 8; r++) { a0[r] = 0.f; a1[r] = 0.f; }
    const float2* Vf2 = (const float2*)Vs;
#pragma unroll
    for (int s4 = 0; s4 < 16; s4++) {
        float2 v0 = Vf2[(s4 * 4 + 0) * 32 + l];
        float2 v1 = Vf2[(s4 * 4 + 1) * 32 + l];
        float2 v2 = Vf2[(s4 * 4 + 2) * 32 + l];
        float2 v3 = Vf2[(s4 * 4 + 3) * 32 + l];
#pragma unroll
        for (int r = 0; r < 8; r++) {
            float4 p4 = Qf4[(w * 8 + r) * 16 + s4];
            a0[r] += p4.x * v0.x + p4.y * v1.x + p4.z * v2.x + p4.w * v3.x;
            a1[r] += p4.x * v0.y + p4.y * v1.y + p4.z * v2.y + p4.w * v3.y;
        }
    }

#pragma unroll
    for (int r = 0; r < 8; r++) {
        int t = w * 8 + r;
        size_t ooff = base + (size_t)t * tstride;
        __nv_bfloat16 h0 = __float2bfloat16_rn(a0[r]);
        __nv_bfloat16 h1 = __float2bfloat16_rn(a1[r]);
        oh[ooff + l]      = h0;
        oh[ooff + l + 32] = h1;
        ol[ooff + l]      = __float2bfloat16_rn(a0[r] - __bfloat162float(h0));
        ol[ooff + l + 32] = __float2bfloat16_rn(a1[r] - __bfloat162float(h1));
    }
}

// ---------------------------------------------------------------------------
// out = LayerNorm(a + b) where b = fp32 OR bf16 hi/lo pair.
// Optional bf16 hi/lo split of out. One warp per 512-dim row.
// ---------------------------------------------------------------------------
__global__ __launch_bounds__(256)
void add_ln(const float* __restrict__ a, const float* __restrict__ bf32,
            const __nv_bfloat162* __restrict__ bh, const __nv_bfloat162* __restrict__ bl,
            float* __restrict__ out,
            __nv_bfloat162* __restrict__ oh, __nv_bfloat162* __restrict__ ol)
{
    int row = blockIdx.x * 8 + (threadIdx.x >> 5);
    int l = threadIdx.x & 31;
    const float4* pa = (const float4*)(a + (size_t)row * 512);

    float4 x[4];
    float s = 0.f;
#pragma unroll
    for (int i = 0; i < 4; i++) {
        float4 u = pa[l + i * 32];
        float4 w;
        if (bf32) {
            w = ((const float4*)(bf32 + (size_t)row * 512))[l + i * 32];
        } else {
            int fi = row * 128 + l + i * 32;
            __nv_bfloat162 h0 = bh[2 * fi], h1 = bh[2 * fi + 1];
            __nv_bfloat162 l0 = bl[2 * fi], l1 = bl[2 * fi + 1];
            w = make_float4(__low2float(h0) + __low2float(l0),
                            __high2float(h0) + __high2float(l0),
                            __low2float(h1) + __low2float(l1),
                            __high2float(h1) + __high2float(l1));
        }
        x[i] = make_float4(u.x + w.x, u.y + w.y, u.z + w.z, u.w + w.w);
        s += x[i].x + x[i].y + x[i].z + x[i].w;
    }
#pragma unroll
    for (int o = 16; o; o >>= 1) s += __shfl_xor_sync(0xffffffffu, s, o);
    float mean = s * (1.f / 512.f);

    float vs = 0.f;
#pragma unroll
    for (int i = 0; i < 4; i++) {
        float dx = x[i].x - mean, dy = x[i].y - mean, dz = x[i].z - mean, dw = x[i].w - mean;
        vs += dx * dx + dy * dy + dz * dz + dw * dw;
    }
#pragma unroll
    for (int o = 16; o; o >>= 1) vs += __shfl_xor_sync(0xffffffffu, vs, o);
    float invstd = rsqrtf(vs * (1.f / 512.f) + 1e-5f);

    float4* po = (float4*)(out + (size_t)row * 512);
#pragma unroll
    for (int i = 0; i < 4; i++) {
        float y0 = (x[i].x - mean) * invstd, y1 = (x[i].y - mean) * invstd;
        float y2 = (x[i].z - mean) * invstd, y3 = (x[i].w - mean) * invstd;
        int fi = row * 128 + l + i * 32;
        po[l + i * 32] = make_float4(y0, y1, y2, y3);
        if (oh) {
            __nv_bfloat162 h0, l0, h1, l1;
            split2(y0, y1, h0, l0);
            split2(y2, y3, h1, l1);
            oh[2 * fi] = h0; oh[2 * fi + 1] = h1;
            ol[2 * fi] = l0; ol[2 * fi + 1] = l1;
        }
    }
}

// ---------------------------------------------------------------------------
// Launch pipeline (graph-capturable: launches only)
// ---------------------------------------------------------------------------
extern "C" void kernel_launch(void* const* d_in, const int* in_sizes, int n_in,
                              void* d_out, int out_size)
{
    const float* xl = (const float*)d_in[0];
    const float* xh = (const float*)d_in[1];
    const float* te = (const float*)d_in[2];
    const float* Wq = (const float*)d_in[3];
    const float* bq = (const float*)d_in[4];
    const float* Wk = (const float*)d_in[5];
    const float* bk = (const float*)d_in[6];
    const float* Wv = (const float*)d_in[7];
    const float* bv = (const float*)d_in[8];
    const float* Wo = (const float*)d_in[9];
    const float* bo = (const float*)d_in[10];
    const float* W1 = (const float*)d_in[11];
    const float* b1 = (const float*)d_in[12];
    const float* W2 = (const float*)d_in[13];
    const float* b2 = (const float*)d_in[14];
    float* out = (float*)d_out;

    float *s2, *s3, *s4;
    __nv_bfloat16 *bf, *wh, *wl;
    cudaGetSymbolAddress((void**)&s2, g_s2);
    cudaGetSymbolAddress((void**)&s3, g_s3);
    cudaGetSymbolAddress((void**)&s4, g_s4);
    cudaGetSymbolAddress((void**)&bf, g_bf);
    cudaGetSymbolAddress((void**)&wh, g_wh);
    cudaGetSymbolAddress((void**)&wl, g_wl);

    __nv_bfloat16* s0h = bf + 0ull * ELEMS;
    __nv_bfloat16* s0l = bf + 1ull * ELEMS;
    __nv_bfloat16* s1h = bf + 2ull * ELEMS;
    __nv_bfloat16* s1l = bf + 3ull * ELEMS;
    __nv_bfloat16* aoh = bf + 4ull * ELEMS;
    __nv_bfloat16* aol = bf + 5ull * ELEMS;
    __nv_bfloat16* vh  = bf + 6ull * ELEMS;
    __nv_bfloat16* vl  = bf + 7ull * ELEMS;
    __nv_bfloat16* f1h = bf + 8ull * ELEMS;
    __nv_bfloat16* f1l = bf + 9ull * ELEMS;

    cudaFuncSetAttribute(gemm_bf3, cudaFuncAttributeMaxDynamicSharedMemorySize, 65536);

    const dim3 gg(4, 1024);
    const dim3 gkv(8, 1024);           // fused K+V
    const int nadd = ELEMS / 4 / 256;

    // 0: weights transpose + split
    prep_w<<<dim3(16, 16, 6), dim3(32, 8)>>>(Wq, Wk, Wv, Wo, W1, W2, wh, wl);
    // 1: fused residual adds + splits (no fp32 copy of xl+te)
    add_te01<<<nadd, 256>>>((const float4*)xl, (const float4*)xh, (const float4*)te,
                            (__nv_bfloat162*)s0h, (__nv_bfloat162*)s0l,
                            (__nv_bfloat162*)s1h, (__nv_bfloat162*)s1l);
    // 2: Q projection
    gemm_bf3<<<gg, 256, 65536>>>(s0h, s0l, wh + 0 * WSZ, wl + 0 * WSZ, bq, s2,
                                 0, 0, 0, 0, 0, 0, 0, 0);
    // 3: fused K+V projection (profiler target)
    gemm_bf3<<<gkv, 256, 65536>>>(s1h, s1l, wh + 1 * WSZ, wl + 1 * WSZ, bk, s3,
                                  0, 0, 1,
                                  wh + 2 * WSZ, wl + 2 * WSZ, bv, s4, 1);
    // 4: attention
    attn64<<<B_ * N_ * H_, 256>>>(s2, s3, s4, aoh, aol);
    // 5: Wo projection
    gemm_bf3<<<gg, 256, 65536>>>(aoh, aol, wh + 3 * WSZ, wl + 3 * WSZ, bo, s3,
                                 0, 0, 0, 0, 0, 0, 0, 0);
    // 6: val = LN(o + (s0h+s0l))
    add_ln<<<TOKENS / 8, 256>>>(s3, 0, (const __nv_bfloat162*)s0h,
                                (const __nv_bfloat162*)s0l, s4,
                                (__nv_bfloat162*)vh, (__nv_bfloat162*)vl);
    // 7: ff1 = relu(val @ W1 + b1)
    gemm_bf3<<<gg, 256, 65536>>>(vh, vl, wh + 4 * WSZ, wl + 4 * WSZ, b1, 0,
                                 f1h, f1l, 1, 0, 0, 0, 0, 0);
    // 8: ff2 = ff1 @ W2 + b2 -> s2
    gemm_bf3<<<gg, 256, 65536>>>(f1h, f1l, wh + 5 * WSZ, wl + 5 * WSZ, b2, s2,
                                 0, 0, 0, 0, 0, 0, 0, 0);
    // 9: out = LN(ff2 + val)
    add_ln<<<TOKENS / 8, 256>>>(s2, s4, 0, 0, out, 0, 0);
}

// round 8
// speedup vs baseline: 1.0758x; 1.0758x over previous
#include <cuda_runtime.h>
#include <cuda_bf16.h>
#include <math.h>
#include <stdint.h>

#define B_ 8
#define T_ 64
#define N_ 256
#define H_ 8
#define D_ 64
#define FEAT 512
#define TOKENS (B_*T_*N_)          /* 131072 */
#define ELEMS  (TOKENS*FEAT)       /* 67108864 */
#define WSZ    (512*512)

// ---------------------------------------------------------------------------
// Scratch (device globals — no cudaMalloc allowed)
// ---------------------------------------------------------------------------
__device__ float g_s2[ELEMS];   // q, later ff2
__device__ float g_s3[ELEMS];   // k, later o (Wo out)
__device__ float g_s4[ELEMS];   // v
__device__ __nv_bfloat16 g_bf[10ull * ELEMS];
__device__ __nv_bfloat16 g_wh[6 * WSZ];
__device__ __nv_bfloat16 g_wl[6 * WSZ];

// ---------------------------------------------------------------------------
// Helpers
// ---------------------------------------------------------------------------
__device__ __forceinline__ uint32_t smem_u32(const void* p) {
    uint32_t a;
    asm("{ .reg .u64 t; cvta.to.shared.u64 t, %1; cvt.u32.u64 %0, t; }" : "=r"(a) : "l"(p));
    return a;
}

__device__ __forceinline__ void cp16(uint32_t dst, const void* src) {
    asm volatile("cp.async.cg.shared.global [%0], [%1], 16;"
                 :: "r"(dst), "l"(__cvta_generic_to_global(src)));
}

__device__ __forceinline__ void ldsm4(uint32_t addr, uint32_t* r) {
    asm volatile("ldmatrix.sync.aligned.m8n8.x4.shared.b16 {%0,%1,%2,%3}, [%4];"
                 : "=r"(r[0]), "=r"(r[1]), "=r"(r[2]), "=r"(r[3]) : "r"(addr));
}

__device__ __forceinline__ void mma_bf16(float* d, const uint32_t* a,
                                         uint32_t b0, uint32_t b1) {
    asm volatile(
        "mma.sync.aligned.m16n8k16.row.col.f32.bf16.bf16.f32 "
        "{%0,%1,%2,%3}, {%4,%5,%6,%7}, {%8,%9}, {%0,%1,%2,%3};"
        : "+f"(d[0]), "+f"(d[1]), "+f"(d[2]), "+f"(d[3])
        : "r"(a[0]), "r"(a[1]), "r"(a[2]), "r"(a[3]), "r"(b0), "r"(b1));
}

__device__ __forceinline__ void split2(float x, float y,
                                       __nv_bfloat162& h, __nv_bfloat162& l) {
    h = __floats2bfloat162_rn(x, y);
    l = __floats2bfloat162_rn(x - __low2float(h), y - __high2float(h));
}

// ---------------------------------------------------------------------------
// Weight prep: transpose + hi/lo split. Wh/Wl[z][n][k] = split(W_z[k][n]).
// ---------------------------------------------------------------------------
__global__ __launch_bounds__(256)
void prep_w(const float* W0, const float* W1, const float* W2,
            const float* W3, const float* W4, const float* W5,
            __nv_bfloat16* __restrict__ Wh, __nv_bfloat16* __restrict__ Wl)
{
    const float* Ws[6] = {W0, W1, W2, W3, W4, W5};
    const float* W = Ws[blockIdx.z];
    __shared__ float t[32][33];
    int bx = blockIdx.x * 32, by = blockIdx.y * 32;
#pragma unroll
    for (int r = 0; r < 32; r += 8)
        t[threadIdx.y + r][threadIdx.x] =
            W[(size_t)(by + threadIdx.y + r) * 512 + bx + threadIdx.x];
    __syncthreads();
    size_t base = (size_t)blockIdx.z * WSZ;
#pragma unroll
    for (int r = 0; r < 32; r += 8) {
        float v = t[threadIdx.x][threadIdx.y + r];
        __nv_bfloat16 h = __float2bfloat16_rn(v);
        size_t o = base + (size_t)(bx + threadIdx.y + r) * 512 + by + threadIdx.x;
        Wh[o] = h;
        Wl[o] = __float2bfloat16_rn(v - __bfloat162float(h));
    }
}

// ---------------------------------------------------------------------------
// Fused residual adds: split(xl+te) -> s0h/l, split(xh+te) -> s1h/l.
// ---------------------------------------------------------------------------
__global__ __launch_bounds__(256)
void add_te01(const float4* __restrict__ xl, const float4* __restrict__ xh,
              const float4* __restrict__ te,
              __nv_bfloat162* __restrict__ h0o, __nv_bfloat162* __restrict__ l0o,
              __nv_bfloat162* __restrict__ h1o, __nv_bfloat162* __restrict__ l1o)
{
    int i = blockIdx.x * 256 + threadIdx.x;
    float4 t = te[i];
    float4 a = xl[i];
    float4 b = xh[i];
    float4 r0 = make_float4(a.x + t.x, a.y + t.y, a.z + t.z, a.w + t.w);
    float4 r1 = make_float4(b.x + t.x, b.y + t.y, b.z + t.z, b.w + t.w);
    __nv_bfloat162 h0, l0, h1, l1;
    split2(r0.x, r0.y, h0, l0);
    split2(r0.z, r0.w, h1, l1);
    h0o[2 * i] = h0; h0o[2 * i + 1] = h1;
    l0o[2 * i] = l0; l0o[2 * i + 1] = l1;
    split2(r1.x, r1.y, h0, l0);
    split2(r1.z, r1.w, h1, l1);
    h1o[2 * i] = h0; h1o[2 * i + 1] = h1;
    l1o[2 * i] = l0; l1o[2 * i + 1] = l1;
}

// ---------------------------------------------------------------------------
// 3xBF16 tensor-core GEMM, 2-stage cp.async pipeline (R6-proven config).
// CTA 128x128, 128 threads, 4 warps (64x64 warp tiles).
// Triple operand set selected by blockIdx.x>>2 (fused Q+K+V projection).
// Set 0 additionally supports bf16 hi/lo output (ff1 path).
// ---------------------------------------------------------------------------
__global__ __launch_bounds__(128, 2)
void gemm_bf3(const __nv_bfloat16* __restrict__ Ah0, const __nv_bfloat16* __restrict__ Al0,
              const __nv_bfloat16* __restrict__ Ah1, const __nv_bfloat16* __restrict__ Al1,
              const __nv_bfloat16* __restrict__ Bh0, const __nv_bfloat16* __restrict__ Bl0,
              const float* __restrict__ bias0, float* __restrict__ Cf0,
              __nv_bfloat16* __restrict__ Ch, __nv_bfloat16* __restrict__ Cl, int relu0,
              const __nv_bfloat16* Bh1, const __nv_bfloat16* Bl1,
              const float* bias1, float* Cf1, int relu1,
              const __nv_bfloat16* Bh2, const __nv_bfloat16* Bl2,
              const float* bias2, float* Cf2, int relu2)
{
    extern __shared__ __align__(128) unsigned char smem[];
    const uint32_t sb = smem_u32(smem);

    const int tid  = threadIdx.x;
    const int lane = tid & 31;
    const int warp = tid >> 5;
    const int wm = warp >> 1, wn = warp & 1;
    const int m0 = blockIdx.y * 128;

    const int set = blockIdx.x >> 2;
    const int n0  = (blockIdx.x & 3) * 128;

    const __nv_bfloat16* AhU = (set == 0) ? Ah0 : Ah1;
    const __nv_bfloat16* AlU = (set == 0) ? Al0 : Al1;
    const __nv_bfloat16* BhU = (set == 0) ? Bh0 : ((set == 1) ? Bh1 : Bh2);
    const __nv_bfloat16* BlU = (set == 0) ? Bl0 : ((set == 1) ? Bl1 : Bl2);
    const float* biasU = (set == 0) ? bias0 : ((set == 1) ? bias1 : bias2);
    float* CfU = (set == 0) ? Cf0 : ((set == 1) ? Cf1 : Cf2);
    const int reluU = (set == 0) ? relu0 : ((set == 1) ? relu1 : relu2);

    const __nv_bfloat16* Ahg = AhU + (size_t)m0 * 512;
    const __nv_bfloat16* Alg = AlU + (size_t)m0 * 512;
    const __nv_bfloat16* Bhg = BhU + (size_t)n0 * 512;
    const __nv_bfloat16* Blg = BlU + (size_t)n0 * 512;

    int frow[4], fc[4];
    uint32_t foff[4];
#pragma unroll
    for (int j = 0; j < 4; j++) {
        int lin = tid + j * 128;
        frow[j] = lin >> 2;
        fc[j]   = lin & 3;
        foff[j] = frow[j] * 64 + ((uint32_t)(fc[j] ^ ((frow[j] >> 1) & 3)) << 4);
    }

#define FILL(kc, st)                                                          \
    do {                                                                      \
        uint32_t s_ = sb + (st) * 32768;                                      \
        _Pragma("unroll")                                                     \
        for (int j = 0; j < 4; j++) {                                         \
            size_t g_ = (size_t)frow[j] * 512 + (kc) * 32 + fc[j] * 8;        \
            cp16(s_ + foff[j],          Ahg + g_);                            \
            cp16(s_ + 8192  + foff[j],  Alg + g_);                            \
            cp16(s_ + 16384 + foff[j],  Bhg + g_);                            \
            cp16(s_ + 24576 + foff[j],  Blg + g_);                            \
        }                                                                     \
        asm volatile("cp.async.commit_group;");                               \
    } while (0)

    float acc[4][8][4];
#pragma unroll
    for (int i = 0; i < 4; i++)
#pragma unroll
        for (int j = 0; j < 8; j++)
#pragma unroll
            for (int k = 0; k < 4; k++) acc[i][j][k] = 0.f;

    const int rA_base = wm * 64 + (lane & 7) + ((lane >> 3) & 1) * 8;
    const uint32_t kbA = ((lane >> 4) & 1) * 16;
    const int rB_base = wn * 64 + (lane & 7) + ((lane >> 4) & 1) * 8;
    const uint32_t kbB = ((lane >> 3) & 1) * 16;

    FILL(0, 0);
    FILL(1, 1);

    for (int c = 0; c < 16; c++) {
        if (c < 15) asm volatile("cp.async.wait_group 1;");
        else        asm volatile("cp.async.wait_group 0;");
        __syncthreads();

        const uint32_t st = (c & 1) * 32768;
        const uint32_t sAh = sb + st, sAl = sAh + 8192;
        const uint32_t sBh = sAh + 16384, sBl = sAh + 24576;

#pragma unroll
        for (int ks = 0; ks < 2; ks++) {
            uint32_t ah[4][4], al[4][4], bh[4][4], bl[4][4];
#pragma unroll
            for (int mt = 0; mt < 4; mt++) {
                int r = rA_base + mt * 16;
                uint32_t kb = kbA + ks * 32;
                uint32_t off = r * 64 + (kb ^ (((r >> 1) & 3) << 4));
                ldsm4(sAh + off, ah[mt]);
                ldsm4(sAl + off, al[mt]);
            }
#pragma unroll
            for (int p = 0; p < 4; p++) {
                int r = rB_base + p * 16;
                uint32_t kb = kbB + ks * 32;
                uint32_t off = r * 64 + (kb ^ (((r >> 1) & 3) << 4));
                ldsm4(sBh + off, bh[p]);
                ldsm4(sBl + off, bl[p]);
            }
#pragma unroll
            for (int mt = 0; mt < 4; mt++)
#pragma unroll
                for (int nt = 0; nt < 8; nt++) {
                    int p = nt >> 1, h = (nt & 1) * 2;
                    mma_bf16(acc[mt][nt], ah[mt], bh[p][h], bh[p][h + 1]);
                    mma_bf16(acc[mt][nt], ah[mt], bl[p][h], bl[p][h + 1]);
                    mma_bf16(acc[mt][nt], al[mt], bh[p][h], bh[p][h + 1]);
                }
        }
        __syncthreads();
        if (c + 2 < 16) FILL(c + 2, (c & 1));
    }

    // ---- epilogue ----
#pragma unroll
    for (int mt = 0; mt < 4; mt++) {
        int row = m0 + wm * 64 + mt * 16 + (lane >> 2);
#pragma unroll
        for (int nt = 0; nt < 8; nt++) {
            int col = n0 + wn * 64 + nt * 8 + (lane & 3) * 2;
            float2 bb = __ldg((const float2*)(biasU + col));
            float v0 = acc[mt][nt][0] + bb.x;
            float v1 = acc[mt][nt][1] + bb.y;
            float v2 = acc[mt][nt][2] + bb.x;
            float v3 = acc[mt][nt][3] + bb.y;
            if (reluU) {
                v0 = fmaxf(v0, 0.f); v1 = fmaxf(v1, 0.f);
                v2 = fmaxf(v2, 0.f); v3 = fmaxf(v3, 0.f);
            }
            if (CfU) {
                *(float2*)(CfU + (size_t)row * 512 + col)       = make_float2(v0, v1);
                *(float2*)(CfU + (size_t)(row + 8) * 512 + col) = make_float2(v2, v3);
            }
            if (set == 0 && Ch) {
                __nv_bfloat162 h0, l0, h1, l1;
                split2(v0, v1, h0, l0);
                split2(v2, v3, h1, l1);
                *(__nv_bfloat162*)(Ch + (size_t)row * 512 + col)       = h0;
                *(__nv_bfloat162*)(Cl + (size_t)row * 512 + col)       = l0;
                *(__nv_bfloat162*)(Ch + (size_t)(row + 8) * 512 + col) = h1;
                *(__nv_bfloat162*)(Cl + (size_t)(row + 8) * 512 + col) = l1;
            }
        }
    }
#undef FILL
}

// ---------------------------------------------------------------------------
// Causal attention per (b, n, h): T=64, D=64. Register-blocked (R6 WIN).
// Masked BEFORE scaling: masked logit = -32767/8.
// ---------------------------------------------------------------------------
__global__ __launch_bounds__(256)
void attn64(const float* __restrict__ q, const float* __restrict__ k,
            const float* __restrict__ v,
            __nv_bfloat16* __restrict__ oh, __nv_bfloat16* __restrict__ ol)
{
    __shared__ float Qs[64 * 64];
    __shared__ float Ks[64 * 64];
    __shared__ float Vs[64 * 64];

    const int idx = blockIdx.x;
    const int h = idx & 7;
    const int n = (idx >> 3) & 255;
    const int b = idx >> 11;
    const size_t base = ((size_t)(b * T_) * N_ + n) * FEAT + h * D_;
    const int tid = threadIdx.x;
    const size_t tstride = (size_t)N_ * FEAT;

    for (int i = tid; i < 4096; i += 256) {
        int t = i >> 6, d = i & 63;
        size_t off = base + (size_t)t * tstride + d;
        Qs[i] = q[off];
        Ks[t * 64 + ((((d >> 2) ^ (t & 7)) << 2) | (d & 3))] = k[off];
        Vs[t * 64 + ((d & 31) * 2 + (d >> 5))] = v[off];
    }
    __syncthreads();

    const int w = tid >> 5;
    const int l = tid & 31;
    const float NEG8 = -4095.875f;
    const float4* Kf4 = (const float4*)Ks;
    const float4* Qf4 = (const float4*)Qs;
    const int csw = l & 7;

    float s0[8], s1[8];
#pragma unroll
    for (int r = 0; r < 8; r++) { s0[r] = 0.f; s1[r] = 0.f; }
#pragma unroll
    for (int c = 0; c < 16; c++) {
        float4 k0 = Kf4[l * 16 + (c ^ csw)];
        float4 k1 = Kf4[(l + 32) * 16 + (c ^ csw)];
#pragma unroll
        for (int r = 0; r < 8; r++) {
            float4 q4 = Qf4[(w * 8 + r) * 16 + c];
            s0[r] += q4.x * k0.x + q4.y * k0.y + q4.z * k0.z + q4.w * k0.w;
            s1[r] += q4.x * k1.x + q4.y * k1.y + q4.z * k1.z + q4.w * k1.w;
        }
    }

#pragma unroll
    for (int r = 0; r < 8; r++) {
        int t = w * 8 + r;
        float l0 = (l      <= t) ? s0[r] * 0.125f : NEG8;
        float l1 = (l + 32 <= t) ? s1[r] * 0.125f : NEG8;
        float m = fmaxf(l0, l1);
#pragma unroll
        for (int o = 16; o; o >>= 1) m = fmaxf(m, __shfl_xor_sync(0xffffffffu, m, o));
        float e0 = __expf(l0 - m), e1 = __expf(l1 - m);
        float sum = e0 + e1;
#pragma unroll
        for (int o = 16; o; o >>= 1) sum += __shfl_xor_sync(0xffffffffu, sum, o);
        float inv = 1.f / sum;
        s0[r] = e0 * inv;
        s1[r] = e1 * inv;
    }

    __syncwarp();
#pragma unroll
    for (int r = 0; r < 8; r++) {
        int t = w * 8 + r;
        Qs[t * 64 + l]      = s0[r];
        Qs[t * 64 + l + 32] = s1[r];
    }
    __syncwarp();

    float a0[8], a1[8];
#pragma unroll
    for (int r = 0; r < 8; r++) { a0[r] = 0.f; a1[r] = 0.f; }
    const float2* Vf2 = (const float2*)Vs;
#pragma unroll
    for (int s4 = 0; s4 < 16; s4++) {
        float2 v0 = Vf2[(s4 * 4 + 0) * 32 + l];
        float2 v1 = Vf2[(s4 * 4 + 1) * 32 + l];
        float2 v2 = Vf2[(s4 * 4 + 2) * 32 + l];
        float2 v3 = Vf2[(s4 * 4 + 3) * 32 + l];
#pragma unroll
        for (int r = 0; r < 8; r++) {
            float4 p4 = Qf4[(w * 8 + r) * 16 + s4];
            a0[r] += p4.x * v0.x + p4.y * v1.x + p4.z * v2.x + p4.w * v3.x;
            a1[r] += p4.x * v0.y + p4.y * v1.y + p4.z * v2.y + p4.w * v3.y;
        }
    }

#pragma unroll
    for (int r = 0; r < 8; r++) {
        int t = w * 8 + r;
        size_t ooff = base + (size_t)t * tstride;
        __nv_bfloat16 h0 = __float2bfloat16_rn(a0[r]);
        __nv_bfloat16 h1 = __float2bfloat16_rn(a1[r]);
        oh[ooff + l]      = h0;
        oh[ooff + l + 32] = h1;
        ol[ooff + l]      = __float2bfloat16_rn(a0[r] - __bfloat162float(h0));
        ol[ooff + l + 32] = __float2bfloat16_rn(a1[r] - __bfloat162float(h1));
    }
}

// ---------------------------------------------------------------------------
// out = LayerNorm(a + (bh+bl)). Optional fp32 out, optional bf16 hi/lo out.
// One warp per 512-dim row.
// ---------------------------------------------------------------------------
__global__ __launch_bounds__(256)
void add_ln(const float* __restrict__ a,
            const __nv_bfloat162* __restrict__ bh, const __nv_bfloat162* __restrict__ bl,
            float* __restrict__ out,
            __nv_bfloat162* __restrict__ oh, __nv_bfloat162* __restrict__ ol)
{
    int row = blockIdx.x * 8 + (threadIdx.x >> 5);
    int l = threadIdx.x & 31;
    const float4* pa = (const float4*)(a + (size_t)row * 512);

    float4 x[4];
    float s = 0.f;
#pragma unroll
    for (int i = 0; i < 4; i++) {
        float4 u = pa[l + i * 32];
        int fi = row * 128 + l + i * 32;
        __nv_bfloat162 h0 = bh[2 * fi], h1 = bh[2 * fi + 1];
        __nv_bfloat162 l0 = bl[2 * fi], l1 = bl[2 * fi + 1];
        float4 w = make_float4(__low2float(h0) + __low2float(l0),
                               __high2float(h0) + __high2float(l0),
                               __low2float(h1) + __low2float(l1),
                               __high2float(h1) + __high2float(l1));
        x[i] = make_float4(u.x + w.x, u.y + w.y, u.z + w.z, u.w + w.w);
        s += x[i].x + x[i].y + x[i].z + x[i].w;
    }
#pragma unroll
    for (int o = 16; o; o >>= 1) s += __shfl_xor_sync(0xffffffffu, s, o);
    float mean = s * (1.f / 512.f);

    float vs = 0.f;
#pragma unroll
    for (int i = 0; i < 4; i++) {
        float dx = x[i].x - mean, dy = x[i].y - mean, dz = x[i].z - mean, dw = x[i].w - mean;
        vs += dx * dx + dy * dy + dz * dz + dw * dw;
    }
#pragma unroll
    for (int o = 16; o; o >>= 1) vs += __shfl_xor_sync(0xffffffffu, vs, o);
    float invstd = rsqrtf(vs * (1.f / 512.f) + 1e-5f);

#pragma unroll
    for (int i = 0; i < 4; i++) {
        float y0 = (x[i].x - mean) * invstd, y1 = (x[i].y - mean) * invstd;
        float y2 = (x[i].z - mean) * invstd, y3 = (x[i].w - mean) * invstd;
        int fi = row * 128 + l + i * 32;
        if (out)
            ((float4*)(out + (size_t)row * 512))[l + i * 32] = make_float4(y0, y1, y2, y3);
        if (oh) {
            __nv_bfloat162 h0, l0, h1, l1;
            split2(y0, y1, h0, l0);
            split2(y2, y3, h1, l1);
            oh[2 * fi] = h0; oh[2 * fi + 1] = h1;
            ol[2 * fi] = l0; ol[2 * fi + 1] = l1;
        }
    }
}

// ---------------------------------------------------------------------------
// Launch pipeline (graph-capturable: launches only)
// ---------------------------------------------------------------------------
extern "C" void kernel_launch(void* const* d_in, const int* in_sizes, int n_in,
                              void* d_out, int out_size)
{
    const float* xl = (const float*)d_in[0];
    const float* xh = (const float*)d_in[1];
    const float* te = (const float*)d_in[2];
    const float* Wq = (const float*)d_in[3];
    const float* bq = (const float*)d_in[4];
    const float* Wk = (const float*)d_in[5];
    const float* bk = (const float*)d_in[6];
    const float* Wv = (const float*)d_in[7];
    const float* bv = (const float*)d_in[8];
    const float* Wo = (const float*)d_in[9];
    const float* bo = (const float*)d_in[10];
    const float* W1 = (const float*)d_in[11];
    const float* b1 = (const float*)d_in[12];
    const float* W2 = (const float*)d_in[13];
    const float* b2 = (const float*)d_in[14];
    float* out = (float*)d_out;

    float *s2, *s3, *s4;
    __nv_bfloat16 *bf, *wh, *wl;
    cudaGetSymbolAddress((void**)&s2, g_s2);
    cudaGetSymbolAddress((void**)&s3, g_s3);
    cudaGetSymbolAddress((void**)&s4, g_s4);
    cudaGetSymbolAddress((void**)&bf, g_bf);
    cudaGetSymbolAddress((void**)&wh, g_wh);
    cudaGetSymbolAddress((void**)&wl, g_wl);

    __nv_bfloat16* s0h = bf + 0ull * ELEMS;
    __nv_bfloat16* s0l = bf + 1ull * ELEMS;
    __nv_bfloat16* s1h = bf + 2ull * ELEMS;
    __nv_bfloat16* s1l = bf + 3ull * ELEMS;
    __nv_bfloat16* aoh = bf + 4ull * ELEMS;
    __nv_bfloat16* aol = bf + 5ull * ELEMS;
    __nv_bfloat16* vh  = bf + 6ull * ELEMS;
    __nv_bfloat16* vl  = bf + 7ull * ELEMS;
    __nv_bfloat16* f1h = bf + 8ull * ELEMS;
    __nv_bfloat16* f1l = bf + 9ull * ELEMS;

    cudaFuncSetAttribute(gemm_bf3, cudaFuncAttributeMaxDynamicSharedMemorySize, 65536);

    const dim3 gg(4, 1024);
    const dim3 gqkv(12, 1024);         // fused Q+K+V
    const int nadd = ELEMS / 4 / 256;

    // 0: weights transpose + split
    prep_w<<<dim3(16, 16, 6), dim3(32, 8)>>>(Wq, Wk, Wv, Wo, W1, W2, wh, wl);
    // 1: fused residual adds + splits
    add_te01<<<nadd, 256>>>((const float4*)xl, (const float4*)xh, (const float4*)te,
                            (__nv_bfloat162*)s0h, (__nv_bfloat162*)s0l,
                            (__nv_bfloat162*)s1h, (__nv_bfloat162*)s1l);
    // 2: fused Q+K+V projection (set0=Q from s0, set1=K relu, set2=V relu from s1)
    gemm_bf3<<<gqkv, 128, 65536>>>(s0h, s0l, s1h, s1l,
                                   wh + 0 * WSZ, wl + 0 * WSZ, bq, s2, 0, 0, 0,
                                   wh + 1 * WSZ, wl + 1 * WSZ, bk, s3, 1,
                                   wh + 2 * WSZ, wl + 2 * WSZ, bv, s4, 1);
    // 3: attention
    attn64<<<B_ * N_ * H_, 256>>>(s2, s3, s4, aoh, aol);
    // 4: Wo projection -> s3 fp32
    gemm_bf3<<<gg, 128, 65536>>>(aoh, aol, 0, 0,
                                 wh + 3 * WSZ, wl + 3 * WSZ, bo, s3, 0, 0, 0,
                                 0, 0, 0, 0, 0, 0, 0, 0, 0, 0);
    // 5: val = LN(o + (s0h+s0l)) -> vh/vl only (no fp32 stream)
    add_ln<<<TOKENS / 8, 256>>>(s3, (const __nv_bfloat162*)s0h,
                                (const __nv_bfloat162*)s0l, 0,
                                (__nv_bfloat162*)vh, (__nv_bfloat162*)vl);
    // 6: ff1 = relu(val @ W1 + b1) -> f1h/f1l
    gemm_bf3<<<gg, 128, 65536>>>(vh, vl, 0, 0,
                                 wh + 4 * WSZ, wl + 4 * WSZ, b1, 0, f1h, f1l, 1,
                                 0, 0, 0, 0, 0, 0, 0, 0, 0, 0);
    // 7: ff2 = ff1 @ W2 + b2 -> s2 fp32
    gemm_bf3<<<gg, 128, 65536>>>(f1h, f1l, 0, 0,
                                 wh + 5 * WSZ, wl + 5 * WSZ, b2, s2, 0, 0, 0,
                                 0, 0, 0, 0, 0, 0, 0, 0, 0, 0);
    // 8: out = LN(ff2 + (vh+vl))
    add_ln<<<TOKENS / 8, 256>>>(s2, (const __nv_bfloat162*)vh,
                                (const __nv_bfloat162*)vl, out, 0, 0);
}

// round 9
// speedup vs baseline: 1.2281x; 1.1416x over previous
#include <cuda_runtime.h>
#include <cuda_bf16.h>
#include <math.h>
#include <stdint.h>

#define B_ 8
#define T_ 64
#define N_ 256
#define H_ 8
#define D_ 64
#define FEAT 512
#define TOKENS (B_*T_*N_)          /* 131072 */
#define ELEMS  (TOKENS*FEAT)       /* 67108864 */
#define WSZ    (512*512)

// ---------------------------------------------------------------------------
// Scratch (device globals — no cudaMalloc allowed)
// ---------------------------------------------------------------------------
__device__ float g_s2[ELEMS];   // ff2 out
__device__ float g_s3[ELEMS];   // Wo out
__device__ __nv_bfloat16 g_bf[16ull * ELEMS];
__device__ __nv_bfloat16 g_wh[6 * WSZ];
__device__ __nv_bfloat16 g_wl[6 * WSZ];

// ---------------------------------------------------------------------------
// Helpers
// ---------------------------------------------------------------------------
__device__ __forceinline__ uint32_t smem_u32(const void* p) {
    uint32_t a;
    asm("{ .reg .u64 t; cvta.to.shared.u64 t, %1; cvt.u32.u64 %0, t; }" : "=r"(a) : "l"(p));
    return a;
}

__device__ __forceinline__ void cp16(uint32_t dst, const void* src) {
    asm volatile("cp.async.cg.shared.global [%0], [%1], 16;"
                 :: "r"(dst), "l"(__cvta_generic_to_global(src)));
}

__device__ __forceinline__ void ldsm4(uint32_t addr, uint32_t* r) {
    asm volatile("ldmatrix.sync.aligned.m8n8.x4.shared.b16 {%0,%1,%2,%3}, [%4];"
                 : "=r"(r[0]), "=r"(r[1]), "=r"(r[2]), "=r"(r[3]) : "r"(addr));
}

__device__ __forceinline__ void ldsm4t(uint32_t addr, uint32_t* r) {
    asm volatile("ldmatrix.sync.aligned.m8n8.x4.trans.shared.b16 {%0,%1,%2,%3}, [%4];"
                 : "=r"(r[0]), "=r"(r[1]), "=r"(r[2]), "=r"(r[3]) : "r"(addr));
}

__device__ __forceinline__ void mma_bf16(float* d, const uint32_t* a,
                                         uint32_t b0, uint32_t b1) {
    asm volatile(
        "mma.sync.aligned.m16n8k16.row.col.f32.bf16.bf16.f32 "
        "{%0,%1,%2,%3}, {%4,%5,%6,%7}, {%8,%9}, {%0,%1,%2,%3};"
        : "+f"(d[0]), "+f"(d[1]), "+f"(d[2]), "+f"(d[3])
        : "r"(a[0]), "r"(a[1]), "r"(a[2]), "r"(a[3]), "r"(b0), "r"(b1));
}

__device__ __forceinline__ void split2(float x, float y,
                                       __nv_bfloat162& h, __nv_bfloat162& l) {
    h = __floats2bfloat162_rn(x, y);
    l = __floats2bfloat162_rn(x - __low2float(h), y - __high2float(h));
}

// ---------------------------------------------------------------------------
// Weight prep: transpose + hi/lo split. Wh/Wl[z][n][k] = split(W_z[k][n]).
// ---------------------------------------------------------------------------
__global__ __launch_bounds__(256)
void prep_w(const float* W0, const float* W1, const float* W2,
            const float* W3, const float* W4, const float* W5,
            __nv_bfloat16* __restrict__ Wh, __nv_bfloat16* __restrict__ Wl)
{
    const float* Ws[6] = {W0, W1, W2, W3, W4, W5};
    const float* W = Ws[blockIdx.z];
    __shared__ float t[32][33];
    int bx = blockIdx.x * 32, by = blockIdx.y * 32;
#pragma unroll
    for (int r = 0; r < 32; r += 8)
        t[threadIdx.y + r][threadIdx.x] =
            W[(size_t)(by + threadIdx.y + r) * 512 + bx + threadIdx.x];
    __syncthreads();
    size_t base = (size_t)blockIdx.z * WSZ;
#pragma unroll
    for (int r = 0; r < 32; r += 8) {
        float v = t[threadIdx.x][threadIdx.y + r];
        __nv_bfloat16 h = __float2bfloat16_rn(v);
        size_t o = base + (size_t)(bx + threadIdx.y + r) * 512 + by + threadIdx.x;
        Wh[o] = h;
        Wl[o] = __float2bfloat16_rn(v - __bfloat162float(h));
    }
}

// ---------------------------------------------------------------------------
// Fused residual adds: split(xl+te) -> s0h/l, split(xh+te) -> s1h/l.
// ---------------------------------------------------------------------------
__global__ __launch_bounds__(256)
void add_te01(const float4* __restrict__ xl, const float4* __restrict__ xh,
              const float4* __restrict__ te,
              __nv_bfloat162* __restrict__ h0o, __nv_bfloat162* __restrict__ l0o,
              __nv_bfloat162* __restrict__ h1o, __nv_bfloat162* __restrict__ l1o)
{
    int i = blockIdx.x * 256 + threadIdx.x;
    float4 t = te[i];
    float4 a = xl[i];
    float4 b = xh[i];
    float4 r0 = make_float4(a.x + t.x, a.y + t.y, a.z + t.z, a.w + t.w);
    float4 r1 = make_float4(b.x + t.x, b.y + t.y, b.z + t.z, b.w + t.w);
    __nv_bfloat162 h0, l0, h1, l1;
    split2(r0.x, r0.y, h0, l0);
    split2(r0.z, r0.w, h1, l1);
    h0o[2 * i] = h0; h0o[2 * i + 1] = h1;
    l0o[2 * i] = l0; l0o[2 * i + 1] = l1;
    split2(r1.x, r1.y, h0, l0);
    split2(r1.z, r1.w, h1, l1);
    h1o[2 * i] = h0; h1o[2 * i + 1] = h1;
    l1o[2 * i] = l0; l1o[2 * i + 1] = l1;
}

// ---------------------------------------------------------------------------
// 3xBF16 tensor-core GEMM, 2-stage cp.async (R6 config). CTA 128x128,
// 128 thr, 4 warps (64x64). Triple operand set via blockIdx.x>>2.
// Each set: optional fp32 out and/or bf16 hi/lo out, optional relu.
// ---------------------------------------------------------------------------
__global__ __launch_bounds__(128, 2)
void gemm_bf3(const __nv_bfloat16* __restrict__ Ah0, const __nv_bfloat16* __restrict__ Al0,
              const __nv_bfloat16* __restrict__ Ah1, const __nv_bfloat16* __restrict__ Al1,
              const __nv_bfloat16* __restrict__ Bh0, const __nv_bfloat16* __restrict__ Bl0,
              const float* bias0, float* Cf0,
              __nv_bfloat16* Ch0, __nv_bfloat16* Cl0, int relu0,
              const __nv_bfloat16* Bh1, const __nv_bfloat16* Bl1,
              const float* bias1, float* Cf1,
              __nv_bfloat16* Ch1, __nv_bfloat16* Cl1, int relu1,
              const __nv_bfloat16* Bh2, const __nv_bfloat16* Bl2,
              const float* bias2, float* Cf2,
              __nv_bfloat16* Ch2, __nv_bfloat16* Cl2, int relu2)
{
    extern __shared__ __align__(128) unsigned char smem[];
    const uint32_t sb = smem_u32(smem);

    const int tid  = threadIdx.x;
    const int lane = tid & 31;
    const int warp = tid >> 5;
    const int wm = warp >> 1, wn = warp & 1;
    const int m0 = blockIdx.y * 128;

    const int set = blockIdx.x >> 2;
    const int n0  = (blockIdx.x & 3) * 128;

    const __nv_bfloat16* AhU = (set == 0) ? Ah0 : Ah1;
    const __nv_bfloat16* AlU = (set == 0) ? Al0 : Al1;
    const __nv_bfloat16* BhU = (set == 0) ? Bh0 : ((set == 1) ? Bh1 : Bh2);
    const __nv_bfloat16* BlU = (set == 0) ? Bl0 : ((set == 1) ? Bl1 : Bl2);
    const float* biasU = (set == 0) ? bias0 : ((set == 1) ? bias1 : bias2);
    float* CfU = (set == 0) ? Cf0 : ((set == 1) ? Cf1 : Cf2);
    __nv_bfloat16* ChU = (set == 0) ? Ch0 : ((set == 1) ? Ch1 : Ch2);
    __nv_bfloat16* ClU = (set == 0) ? Cl0 : ((set == 1) ? Cl1 : Cl2);
    const int reluU = (set == 0) ? relu0 : ((set == 1) ? relu1 : relu2);

    const __nv_bfloat16* Ahg = AhU + (size_t)m0 * 512;
    const __nv_bfloat16* Alg = AlU + (size_t)m0 * 512;
    const __nv_bfloat16* Bhg = BhU + (size_t)n0 * 512;
    const __nv_bfloat16* Blg = BlU + (size_t)n0 * 512;

    int frow[4], fc[4];
    uint32_t foff[4];
#pragma unroll
    for (int j = 0; j < 4; j++) {
        int lin = tid + j * 128;
        frow[j] = lin >> 2;
        fc[j]   = lin & 3;
        foff[j] = frow[j] * 64 + ((uint32_t)(fc[j] ^ ((frow[j] >> 1) & 3)) << 4);
    }

#define FILL(kc, st)                                                          \
    do {                                                                      \
        uint32_t s_ = sb + (st) * 32768;                                      \
        _Pragma("unroll")                                                     \
        for (int j = 0; j < 4; j++) {                                         \
            size_t g_ = (size_t)frow[j] * 512 + (kc) * 32 + fc[j] * 8;        \
            cp16(s_ + foff[j],          Ahg + g_);                            \
            cp16(s_ + 8192  + foff[j],  Alg + g_);                            \
            cp16(s_ + 16384 + foff[j],  Bhg + g_);                            \
            cp16(s_ + 24576 + foff[j],  Blg + g_);                            \
        }                                                                     \
        asm volatile("cp.async.commit_group;");                               \
    } while (0)

    float acc[4][8][4];
#pragma unroll
    for (int i = 0; i < 4; i++)
#pragma unroll
        for (int j = 0; j < 8; j++)
#pragma unroll
            for (int k = 0; k < 4; k++) acc[i][j][k] = 0.f;

    const int rA_base = wm * 64 + (lane & 7) + ((lane >> 3) & 1) * 8;
    const uint32_t kbA = ((lane >> 4) & 1) * 16;
    const int rB_base = wn * 64 + (lane & 7) + ((lane >> 4) & 1) * 8;
    const uint32_t kbB = ((lane >> 3) & 1) * 16;

    FILL(0, 0);
    FILL(1, 1);

    for (int c = 0; c < 16; c++) {
        if (c < 15) asm volatile("cp.async.wait_group 1;");
        else        asm volatile("cp.async.wait_group 0;");
        __syncthreads();

        const uint32_t st = (c & 1) * 32768;
        const uint32_t sAh = sb + st, sAl = sAh + 8192;
        const uint32_t sBh = sAh + 16384, sBl = sAh + 24576;

#pragma unroll
        for (int ks = 0; ks < 2; ks++) {
            uint32_t ah[4][4], al[4][4], bh[4][4], bl[4][4];
#pragma unroll
            for (int mt = 0; mt < 4; mt++) {
                int r = rA_base + mt * 16;
                uint32_t kb = kbA + ks * 32;
                uint32_t off = r * 64 + (kb ^ (((r >> 1) & 3) << 4));
                ldsm4(sAh + off, ah[mt]);
                ldsm4(sAl + off, al[mt]);
            }
#pragma unroll
            for (int p = 0; p < 4; p++) {
                int r = rB_base + p * 16;
                uint32_t kb = kbB + ks * 32;
                uint32_t off = r * 64 + (kb ^ (((r >> 1) & 3) << 4));
                ldsm4(sBh + off, bh[p]);
                ldsm4(sBl + off, bl[p]);
            }
#pragma unroll
            for (int mt = 0; mt < 4; mt++)
#pragma unroll
                for (int nt = 0; nt < 8; nt++) {
                    int p = nt >> 1, h = (nt & 1) * 2;
                    mma_bf16(acc[mt][nt], ah[mt], bh[p][h], bh[p][h + 1]);
                    mma_bf16(acc[mt][nt], ah[mt], bl[p][h], bl[p][h + 1]);
                    mma_bf16(acc[mt][nt], al[mt], bh[p][h], bh[p][h + 1]);
                }
        }
        __syncthreads();
        if (c + 2 < 16) FILL(c + 2, (c & 1));
    }

    // ---- epilogue ----
#pragma unroll
    for (int mt = 0; mt < 4; mt++) {
        int row = m0 + wm * 64 + mt * 16 + (lane >> 2);
#pragma unroll
        for (int nt = 0; nt < 8; nt++) {
            int col = n0 + wn * 64 + nt * 8 + (lane & 3) * 2;
            float2 bb = __ldg((const float2*)(biasU + col));
            float v0 = acc[mt][nt][0] + bb.x;
            float v1 = acc[mt][nt][1] + bb.y;
            float v2 = acc[mt][nt][2] + bb.x;
            float v3 = acc[mt][nt][3] + bb.y;
            if (reluU) {
                v0 = fmaxf(v0, 0.f); v1 = fmaxf(v1, 0.f);
                v2 = fmaxf(v2, 0.f); v3 = fmaxf(v3, 0.f);
            }
            if (CfU) {
                *(float2*)(CfU + (size_t)row * 512 + col)       = make_float2(v0, v1);
                *(float2*)(CfU + (size_t)(row + 8) * 512 + col) = make_float2(v2, v3);
            }
            if (ChU) {
                __nv_bfloat162 h0, l0, h1, l1;
                split2(v0, v1, h0, l0);
                split2(v2, v3, h1, l1);
                *(__nv_bfloat162*)(ChU + (size_t)row * 512 + col)       = h0;
                *(__nv_bfloat162*)(ClU + (size_t)row * 512 + col)       = l0;
                *(__nv_bfloat162*)(ChU + (size_t)(row + 8) * 512 + col) = h1;
                *(__nv_bfloat162*)(ClU + (size_t)(row + 8) * 512 + col) = l1;
            }
        }
    }
#undef FILL
}

// ---------------------------------------------------------------------------
// Tensor-core causal attention per (b,n,h): T=64, D=64. 128 threads, 4 warps.
// Warp w owns rows 16w..16w+15. S = QK^T (3xbf16 MMA, fp32 acc); softmax in
// fragments; P hi/lo overwrites warp-own Q smem rows; O = PV with V loaded
// via ldmatrix.trans. Masked BEFORE scaling: masked logit = -32767/8.
// smem rows: 64 x 128B, 16B-chunk swizzle q^(row&7).
// ---------------------------------------------------------------------------
__global__ __launch_bounds__(128)
void attn_mma(const __nv_bfloat16* __restrict__ qh, const __nv_bfloat16* __restrict__ ql,
              const __nv_bfloat16* __restrict__ kh, const __nv_bfloat16* __restrict__ kl,
              const __nv_bfloat16* __restrict__ vh, const __nv_bfloat16* __restrict__ vl,
              __nv_bfloat16* __restrict__ oh, __nv_bfloat16* __restrict__ ol)
{
    __shared__ __align__(128) unsigned char sm[6 * 8192];  // Qh Ql Kh Kl Vh Vl
    const uint32_t sb = smem_u32(sm);
    const uint32_t sQh = sb, sQl = sb + 8192;
    const uint32_t sKh = sb + 16384, sKl = sb + 24576;
    const uint32_t sVh = sb + 32768, sVl = sb + 40960;

    const int idx = blockIdx.x;
    const int h = idx & 7;
    const int n = (idx >> 3) & 255;
    const int b = idx >> 11;
    const size_t base = ((size_t)(b * T_) * N_ + n) * FEAT + h * D_;
    const int tid = threadIdx.x;
    const size_t tstride = (size_t)N_ * FEAT;

    // ---- load 6 x 64x64 bf16 tiles (swizzled) ----
#define LOADM(ptr, moff)                                                      \
    _Pragma("unroll")                                                         \
    for (int i = 0; i < 4; i++) {                                             \
        int lin = tid + i * 128;                                              \
        int t_ = lin >> 3, q_ = lin & 7;                                      \
        cp16(sb + (moff) + t_ * 128 + ((q_ ^ (t_ & 7)) << 4),                 \
             (ptr) + base + (size_t)t_ * tstride + q_ * 8);                   \
    }
    LOADM(qh, 0);
    LOADM(ql, 8192);
    LOADM(kh, 16384);
    LOADM(kl, 24576);
    LOADM(vh, 32768);
    LOADM(vl, 40960);
#undef LOADM
    asm volatile("cp.async.commit_group;");
    asm volatile("cp.async.wait_group 0;");
    __syncthreads();

    const int w = tid >> 5;
    const int lane = tid & 31;
    const int m0 = w * 16;
    const float NEG8 = -4095.875f;

    // ---- QK^T ----
    uint32_t aqh[4][4], aql[4][4];
    {
        int r = m0 + (lane & 7) + ((lane >> 3) & 1) * 8;
        int qc = lane >> 4;
#pragma unroll
        for (int ks = 0; ks < 4; ks++) {
            uint32_t off = r * 128 + (((ks * 2 + qc) ^ (r & 7)) << 4);
            ldsm4(sQh + off, aqh[ks]);
            ldsm4(sQl + off, aql[ks]);
        }
    }

    float acc[8][4];
#pragma unroll
    for (int i = 0; i < 8; i++)
#pragma unroll
        for (int j = 0; j < 4; j++) acc[i][j] = 0.f;

    {
        int rn = (lane & 7) + ((lane >> 4) & 1) * 8;
        int kc = (lane >> 3) & 1;
#pragma unroll
        for (int p = 0; p < 4; p++) {
            int rt = p * 16 + rn;
#pragma unroll
            for (int ks = 0; ks < 4; ks++) {
                uint32_t off = rt * 128 + (((ks * 2 + kc) ^ (rt & 7)) << 4);
                uint32_t bh[4], bl[4];
                ldsm4(sKh + off, bh);
                ldsm4(sKl + off, bl);
                mma_bf16(acc[2 * p],     aqh[ks], bh[0], bh[1]);
                mma_bf16(acc[2 * p],     aqh[ks], bl[0], bl[1]);
                mma_bf16(acc[2 * p],     aql[ks], bh[0], bh[1]);
                mma_bf16(acc[2 * p + 1], aqh[ks], bh[2], bh[3]);
                mma_bf16(acc[2 * p + 1], aqh[ks], bl[2], bl[3]);
                mma_bf16(acc[2 * p + 1], aql[ks], bh[2], bh[3]);
            }
        }
    }

    // ---- softmax (mask before scale) ----
    const int colb = (lane & 3) * 2;
    const int r0 = m0 + (lane >> 2), r1 = r0 + 8;
    float m0v = NEG8, m1v = NEG8;
#pragma unroll
    for (int nt = 0; nt < 8; nt++) {
        int c = nt * 8 + colb;
        acc[nt][0] = (c     <= r0) ? acc[nt][0] * 0.125f : NEG8;
        acc[nt][1] = (c + 1 <= r0) ? acc[nt][1] * 0.125f : NEG8;
        acc[nt][2] = (c     <= r1) ? acc[nt][2] * 0.125f : NEG8;
        acc[nt][3] = (c + 1 <= r1) ? acc[nt][3] * 0.125f : NEG8;
        m0v = fmaxf(m0v, fmaxf(acc[nt][0], acc[nt][1]));
        m1v = fmaxf(m1v, fmaxf(acc[nt][2], acc[nt][3]));
    }
    m0v = fmaxf(m0v, __shfl_xor_sync(0xffffffffu, m0v, 1));
    m0v = fmaxf(m0v, __shfl_xor_sync(0xffffffffu, m0v, 2));
    m1v = fmaxf(m1v, __shfl_xor_sync(0xffffffffu, m1v, 1));
    m1v = fmaxf(m1v, __shfl_xor_sync(0xffffffffu, m1v, 2));

    float sum0 = 0.f, sum1 = 0.f;
#pragma unroll
    for (int nt = 0; nt < 8; nt++) {
        acc[nt][0] = __expf(acc[nt][0] - m0v);
        acc[nt][1] = __expf(acc[nt][1] - m0v);
        acc[nt][2] = __expf(acc[nt][2] - m1v);
        acc[nt][3] = __expf(acc[nt][3] - m1v);
        sum0 += acc[nt][0] + acc[nt][1];
        sum1 += acc[nt][2] + acc[nt][3];
    }
    sum0 += __shfl_xor_sync(0xffffffffu, sum0, 1);
    sum0 += __shfl_xor_sync(0xffffffffu, sum0, 2);
    sum1 += __shfl_xor_sync(0xffffffffu, sum1, 1);
    sum1 += __shfl_xor_sync(0xffffffffu, sum1, 2);
    const float inv0 = 1.f / sum0, inv1 = 1.f / sum1;

    // ---- write P hi/lo into this warp's own Q smem rows ----
#pragma unroll
    for (int nt = 0; nt < 8; nt++) {
        __nv_bfloat162 hh, ll;
        split2(acc[nt][0] * inv0, acc[nt][1] * inv0, hh, ll);
        uint32_t o0 = r0 * 128 + ((nt ^ (r0 & 7)) << 4) + colb * 2;
        *(__nv_bfloat162*)(sm + o0)        = hh;
        *(__nv_bfloat162*)(sm + 8192 + o0) = ll;
        split2(acc[nt][2] * inv1, acc[nt][3] * inv1, hh, ll);
        uint32_t o1 = r1 * 128 + ((nt ^ (r1 & 7)) << 4) + colb * 2;
        *(__nv_bfloat162*)(sm + o1)        = hh;
        *(__nv_bfloat162*)(sm + 8192 + o1) = ll;
    }
    __syncwarp();

    // ---- O = P V ----
    float accO[8][4];
#pragma unroll
    for (int i = 0; i < 8; i++)
#pragma unroll
        for (int j = 0; j < 4; j++) accO[i][j] = 0.f;

    {
        int rp = m0 + (lane & 7) + ((lane >> 3) & 1) * 8;
        int pqc = lane >> 4;
        int sv = lane & 15;
        int vqc = lane >> 4;
#pragma unroll
        for (int ks = 0; ks < 4; ks++) {
            uint32_t offP = rp * 128 + (((ks * 2 + pqc) ^ (rp & 7)) << 4);
            uint32_t aph[4], apl[4];
            ldsm4(sQh + offP, aph);
            ldsm4(sQl + offP, apl);
            int rv = ks * 16 + sv;
#pragma unroll
            for (int dt = 0; dt < 4; dt++) {
                uint32_t offV = rv * 128 + (((dt * 2 + vqc) ^ (rv & 7)) << 4);
                uint32_t bh[4], bl[4];
                ldsm4t(sVh + offV, bh);
                ldsm4t(sVl + offV, bl);
                mma_bf16(accO[2 * dt],     aph, bh[0], bh[1]);
                mma_bf16(accO[2 * dt],     aph, bl[0], bl[1]);
                mma_bf16(accO[2 * dt],     apl, bh[0], bh[1]);
                mma_bf16(accO[2 * dt + 1], aph, bh[2], bh[3]);
                mma_bf16(accO[2 * dt + 1], aph, bl[2], bl[3]);
                mma_bf16(accO[2 * dt + 1], apl, bh[2], bh[3]);
            }
        }
    }

    // ---- store O hi/lo ----
#pragma unroll
    for (int nt = 0; nt < 8; nt++) {
        int col = nt * 8 + colb;
        __nv_bfloat162 hh, ll;
        split2(accO[nt][0], accO[nt][1], hh, ll);
        size_t o0 = base + (size_t)r0 * tstride + col;
        *(__nv_bfloat162*)(oh + o0) = hh;
        *(__nv_bfloat162*)(ol + o0) = ll;
        split2(accO[nt][2], accO[nt][3], hh, ll);
        size_t o1 = base + (size_t)r1 * tstride + col;
        *(__nv_bfloat162*)(oh + o1) = hh;
        *(__nv_bfloat162*)(ol + o1) = ll;
    }
}

// ---------------------------------------------------------------------------
// out = LayerNorm(a + (bh+bl)). Optional fp32 out, optional bf16 hi/lo out.
// ---------------------------------------------------------------------------
__global__ __launch_bounds__(256)
void add_ln(const float* __restrict__ a,
            const __nv_bfloat162* __restrict__ bh, const __nv_bfloat162* __restrict__ bl,
            float* __restrict__ out,
            __nv_bfloat162* __restrict__ oh, __nv_bfloat162* __restrict__ ol)
{
    int row = blockIdx.x * 8 + (threadIdx.x >> 5);
    int l = threadIdx.x & 31;
    const float4* pa = (const float4*)(a + (size_t)row * 512);

    float4 x[4];
    float s = 0.f;
#pragma unroll
    for (int i = 0; i < 4; i++) {
        float4 u = pa[l + i * 32];
        int fi = row * 128 + l + i * 32;
        __nv_bfloat162 h0 = bh[2 * fi], h1 = bh[2 * fi + 1];
        __nv_bfloat162 l0 = bl[2 * fi], l1 = bl[2 * fi + 1];
        float4 w = make_float4(__low2float(h0) + __low2float(l0),
                               __high2float(h0) + __high2float(l0),
                               __low2float(h1) + __low2float(l1),
                               __high2float(h1) + __high2float(l1));
        x[i] = make_float4(u.x + w.x, u.y + w.y, u.z + w.z, u.w + w.w);
        s += x[i].x + x[i].y + x[i].z + x[i].w;
    }
#pragma unroll
    for (int o = 16; o; o >>= 1) s += __shfl_xor_sync(0xffffffffu, s, o);
    float mean = s * (1.f / 512.f);

    float vs = 0.f;
#pragma unroll
    for (int i = 0; i < 4; i++) {
        float dx = x[i].x - mean, dy = x[i].y - mean, dz = x[i].z - mean, dw = x[i].w - mean;
        vs += dx * dx + dy * dy + dz * dz + dw * dw;
    }
#pragma unroll
    for (int o = 16; o; o >>= 1) vs += __shfl_xor_sync(0xffffffffu, vs, o);
    float invstd = rsqrtf(vs * (1.f / 512.f) + 1e-5f);

#pragma unroll
    for (int i = 0; i < 4; i++) {
        float y0 = (x[i].x - mean) * invstd, y1 = (x[i].y - mean) * invstd;
        float y2 = (x[i].z - mean) * invstd, y3 = (x[i].w - mean) * invstd;
        int fi = row * 128 + l + i * 32;
        if (out)
            ((float4*)(out + (size_t)row * 512))[l + i * 32] = make_float4(y0, y1, y2, y3);
        if (oh) {
            __nv_bfloat162 h0, l0, h1, l1;
            split2(y0, y1, h0, l0);
            split2(y2, y3, h1, l1);
            oh[2 * fi] = h0; oh[2 * fi + 1] = h1;
            ol[2 * fi] = l0; ol[2 * fi + 1] = l1;
        }
    }
}

// ---------------------------------------------------------------------------
// Launch pipeline (graph-capturable: launches only)
// ---------------------------------------------------------------------------
extern "C" void kernel_launch(void* const* d_in, const int* in_sizes, int n_in,
                              void* d_out, int out_size)
{
    const float* xl = (const float*)d_in[0];
    const float* xh = (const float*)d_in[1];
    const float* te = (const float*)d_in[2];
    const float* Wq = (const float*)d_in[3];
    const float* bq = (const float*)d_in[4];
    const float* Wk = (const float*)d_in[5];
    const float* bk = (const float*)d_in[6];
    const float* Wv = (const float*)d_in[7];
    const float* bv = (const float*)d_in[8];
    const float* Wo = (const float*)d_in[9];
    const float* bo = (const float*)d_in[10];
    const float* W1 = (const float*)d_in[11];
    const float* b1 = (const float*)d_in[12];
    const float* W2 = (const float*)d_in[13];
    const float* b2 = (const float*)d_in[14];
    float* out = (float*)d_out;

    float *s2, *s3;
    __nv_bfloat16 *bf, *wh, *wl;
    cudaGetSymbolAddress((void**)&s2, g_s2);
    cudaGetSymbolAddress((void**)&s3, g_s3);
    cudaGetSymbolAddress((void**)&bf, g_bf);
    cudaGetSymbolAddress((void**)&wh, g_wh);
    cudaGetSymbolAddress((void**)&wl, g_wl);

    __nv_bfloat16* s0h = bf + 0ull  * ELEMS;
    __nv_bfloat16* s0l = bf + 1ull  * ELEMS;
    __nv_bfloat16* s1h = bf + 2ull  * ELEMS;
    __nv_bfloat16* s1l = bf + 3ull  * ELEMS;
    __nv_bfloat16* qh  = bf + 4ull  * ELEMS;
    __nv_bfloat16* ql  = bf + 5ull  * ELEMS;
    __nv_bfloat16* kh  = bf + 6ull  * ELEMS;
    __nv_bfloat16* kl  = bf + 7ull  * ELEMS;
    __nv_bfloat16* vvh = bf + 8ull  * ELEMS;
    __nv_bfloat16* vvl = bf + 9ull  * ELEMS;
    __nv_bfloat16* aoh = bf + 10ull * ELEMS;
    __nv_bfloat16* aol = bf + 11ull * ELEMS;
    __nv_bfloat16* vah = bf + 12ull * ELEMS;
    __nv_bfloat16* val_ = bf + 13ull * ELEMS;
    __nv_bfloat16* f1h = bf + 14ull * ELEMS;
    __nv_bfloat16* f1l = bf + 15ull * ELEMS;

    cudaFuncSetAttribute(gemm_bf3, cudaFuncAttributeMaxDynamicSharedMemorySize, 65536);

    const dim3 gg(4, 1024);
    const dim3 gqkv(12, 1024);
    const int nadd = ELEMS / 4 / 256;

    // 0: weights transpose + split
    prep_w<<<dim3(16, 16, 6), dim3(32, 8)>>>(Wq, Wk, Wv, Wo, W1, W2, wh, wl);
    // 1: fused residual adds + splits
    add_te01<<<nadd, 256>>>((const float4*)xl, (const float4*)xh, (const float4*)te,
                            (__nv_bfloat162*)s0h, (__nv_bfloat162*)s0l,
                            (__nv_bfloat162*)s1h, (__nv_bfloat162*)s1l);
    // 2: fused Q+K+V projection -> bf16 hi/lo pairs
    gemm_bf3<<<gqkv, 128, 65536>>>(s0h, s0l, s1h, s1l,
                                   wh + 0 * WSZ, wl + 0 * WSZ, bq, 0, qh, ql, 0,
                                   wh + 1 * WSZ, wl + 1 * WSZ, bk, 0, kh, kl, 1,
                                   wh + 2 * WSZ, wl + 2 * WSZ, bv, 0, vvh, vvl, 1);
    // 3: tensor-core attention
    attn_mma<<<B_ * N_ * H_, 128>>>(qh, ql, kh, kl, vvh, vvl, aoh, aol);
    // 4: Wo projection -> s3 fp32
    gemm_bf3<<<gg, 128, 65536>>>(aoh, aol, 0, 0,
                                 wh + 3 * WSZ, wl + 3 * WSZ, bo, s3, 0, 0, 0,
                                 0, 0, 0, 0, 0, 0, 0,
                                 0, 0, 0, 0, 0, 0, 0);
    // 5: val = LN(o + (s0h+s0l)) -> vah/val_ (bf16 only)
    add_ln<<<TOKENS / 8, 256>>>(s3, (const __nv_bfloat162*)s0h,
                                (const __nv_bfloat162*)s0l, 0,
                                (__nv_bfloat162*)vah, (__nv_bfloat162*)val_);
    // 6: ff1 = relu(val @ W1 + b1) -> f1h/f1l
    gemm_bf3<<<gg, 128, 65536>>>(vah, val_, 0, 0,
                                 wh + 4 * WSZ, wl + 4 * WSZ, b1, 0, f1h, f1l, 1,
                                 0, 0, 0, 0, 0, 0, 0,
                                 0, 0, 0, 0, 0, 0, 0);
    // 7: ff2 = ff1 @ W2 + b2 -> s2 fp32
    gemm_bf3<<<gg, 128, 65536>>>(f1h, f1l, 0, 0,
                                 wh + 5 * WSZ, wl + 5 * WSZ, b2, s2, 0, 0, 0,
                                 0, 0, 0, 0, 0, 0, 0,
                                 0, 0, 0, 0, 0, 0, 0);
    // 8: out = LN(ff2 + (vah+val_))
    add_ln<<<TOKENS / 8, 256>>>(s2, (const __nv_bfloat162*)vah,
                                (const __nv_bfloat162*)val_, out, 0, 0);
}

// round 10
// speedup vs baseline: 1.2285x; 1.0004x over previous
#include <cuda_runtime.h>
#include <cuda_bf16.h>
#include <math.h>
#include <stdint.h>

#define B_ 8
#define T_ 64
#define N_ 256
#define H_ 8
#define D_ 64
#define FEAT 512
#define TOKENS (B_*T_*N_)          /* 131072 */
#define ELEMS  (TOKENS*FEAT)       /* 67108864 */
#define WSZ    (512*512)

// ---------------------------------------------------------------------------
// Scratch (device globals — no cudaMalloc allowed)
// ---------------------------------------------------------------------------
__device__ float g_s2[ELEMS];   // ff2 out
__device__ float g_s3[ELEMS];   // Wo out
__device__ __nv_bfloat16 g_bf[16ull * ELEMS];
__device__ __nv_bfloat16 g_wh[6 * WSZ];
__device__ __nv_bfloat16 g_wl[6 * WSZ];

// ---------------------------------------------------------------------------
// Helpers
// ---------------------------------------------------------------------------
__device__ __forceinline__ uint32_t smem_u32(const void* p) {
    uint32_t a;
    asm("{ .reg .u64 t; cvta.to.shared.u64 t, %1; cvt.u32.u64 %0, t; }" : "=r"(a) : "l"(p));
    return a;
}

__device__ __forceinline__ void cp16(uint32_t dst, const void* src) {
    asm volatile("cp.async.cg.shared.global [%0], [%1], 16;"
                 :: "r"(dst), "l"(__cvta_generic_to_global(src)));
}

__device__ __forceinline__ void ldsm4(uint32_t addr, uint32_t* r) {
    asm volatile("ldmatrix.sync.aligned.m8n8.x4.shared.b16 {%0,%1,%2,%3}, [%4];"
                 : "=r"(r[0]), "=r"(r[1]), "=r"(r[2]), "=r"(r[3]) : "r"(addr));
}

__device__ __forceinline__ void ldsm4t(uint32_t addr, uint32_t* r) {
    asm volatile("ldmatrix.sync.aligned.m8n8.x4.trans.shared.b16 {%0,%1,%2,%3}, [%4];"
                 : "=r"(r[0]), "=r"(r[1]), "=r"(r[2]), "=r"(r[3]) : "r"(addr));
}

__device__ __forceinline__ void mma_bf16(float* d, const uint32_t* a,
                                         uint32_t b0, uint32_t b1) {
    asm volatile(
        "mma.sync.aligned.m16n8k16.row.col.f32.bf16.bf16.f32 "
        "{%0,%1,%2,%3}, {%4,%5,%6,%7}, {%8,%9}, {%0,%1,%2,%3};"
        : "+f"(d[0]), "+f"(d[1]), "+f"(d[2]), "+f"(d[3])
        : "r"(a[0]), "r"(a[1]), "r"(a[2]), "r"(a[3]), "r"(b0), "r"(b1));
}

__device__ __forceinline__ void split2(float x, float y,
                                       __nv_bfloat162& h, __nv_bfloat162& l) {
    h = __floats2bfloat162_rn(x, y);
    l = __floats2bfloat162_rn(x - __low2float(h), y - __high2float(h));
}

// ---------------------------------------------------------------------------
// Weight prep: transpose + hi/lo split. Wh/Wl[z][n][k] = split(W_z[k][n]).
// ---------------------------------------------------------------------------
__global__ __launch_bounds__(256)
void prep_w(const float* W0, const float* W1, const float* W2,
            const float* W3, const float* W4, const float* W5,
            __nv_bfloat16* __restrict__ Wh, __nv_bfloat16* __restrict__ Wl)
{
    const float* Ws[6] = {W0, W1, W2, W3, W4, W5};
    const float* W = Ws[blockIdx.z];
    __shared__ float t[32][33];
    int bx = blockIdx.x * 32, by = blockIdx.y * 32;
#pragma unroll
    for (int r = 0; r < 32; r += 8)
        t[threadIdx.y + r][threadIdx.x] =
            W[(size_t)(by + threadIdx.y + r) * 512 + bx + threadIdx.x];
    __syncthreads();
    size_t base = (size_t)blockIdx.z * WSZ;
#pragma unroll
    for (int r = 0; r < 32; r += 8) {
        float v = t[threadIdx.x][threadIdx.y + r];
        __nv_bfloat16 h = __float2bfloat16_rn(v);
        size_t o = base + (size_t)(bx + threadIdx.y + r) * 512 + by + threadIdx.x;
        Wh[o] = h;
        Wl[o] = __float2bfloat16_rn(v - __bfloat162float(h));
    }
}

// ---------------------------------------------------------------------------
// Fused residual adds: split(xl+te) -> s0h/l, split(xh+te) -> s1h/l.
// ---------------------------------------------------------------------------
__global__ __launch_bounds__(256)
void add_te01(const float4* __restrict__ xl, const float4* __restrict__ xh,
              const float4* __restrict__ te,
              __nv_bfloat162* __restrict__ h0o, __nv_bfloat162* __restrict__ l0o,
              __nv_bfloat162* __restrict__ h1o, __nv_bfloat162* __restrict__ l1o)
{
    int i = blockIdx.x * 256 + threadIdx.x;
    float4 t = te[i];
    float4 a = xl[i];
    float4 b = xh[i];
    float4 r0 = make_float4(a.x + t.x, a.y + t.y, a.z + t.z, a.w + t.w);
    float4 r1 = make_float4(b.x + t.x, b.y + t.y, b.z + t.z, b.w + t.w);
    __nv_bfloat162 h0, l0, h1, l1;
    split2(r0.x, r0.y, h0, l0);
    split2(r0.z, r0.w, h1, l1);
    h0o[2 * i] = h0; h0o[2 * i + 1] = h1;
    l0o[2 * i] = l0; l0o[2 * i + 1] = l1;
    split2(r1.x, r1.y, h0, l0);
    split2(r1.z, r1.w, h1, l1);
    h1o[2 * i] = h0; h1o[2 * i + 1] = h1;
    l1o[2 * i] = l0; l1o[2 * i + 1] = l1;
}

// ---------------------------------------------------------------------------
// 3xBF16 tensor-core GEMM, 2-stage cp.async. CTA 128x128, 128 thr, 4 warps
// (64x64). MMAs issued in 3 passes (hh / hl / lh) so same-accumulator reuse
// distance is 32 instead of 1 (HMMA RAW chain breaker; bit-exact order per
// accumulator). Triple operand set via blockIdx.x>>2.
// ---------------------------------------------------------------------------
__global__ __launch_bounds__(128, 2)
void gemm_bf3(const __nv_bfloat16* __restrict__ Ah0, const __nv_bfloat16* __restrict__ Al0,
              const __nv_bfloat16* __restrict__ Ah1, const __nv_bfloat16* __restrict__ Al1,
              const __nv_bfloat16* __restrict__ Bh0, const __nv_bfloat16* __restrict__ Bl0,
              const float* bias0, float* Cf0,
              __nv_bfloat16* Ch0, __nv_bfloat16* Cl0, int relu0,
              const __nv_bfloat16* Bh1, const __nv_bfloat16* Bl1,
              const float* bias1, float* Cf1,
              __nv_bfloat16* Ch1, __nv_bfloat16* Cl1, int relu1,
              const __nv_bfloat16* Bh2, const __nv_bfloat16* Bl2,
              const float* bias2, float* Cf2,
              __nv_bfloat16* Ch2, __nv_bfloat16* Cl2, int relu2)
{
    extern __shared__ __align__(128) unsigned char smem[];
    const uint32_t sb = smem_u32(smem);

    const int tid  = threadIdx.x;
    const int lane = tid & 31;
    const int warp = tid >> 5;
    const int wm = warp >> 1, wn = warp & 1;
    const int m0 = blockIdx.y * 128;

    const int set = blockIdx.x >> 2;
    const int n0  = (blockIdx.x & 3) * 128;

    const __nv_bfloat16* AhU = (set == 0) ? Ah0 : Ah1;
    const __nv_bfloat16* AlU = (set == 0) ? Al0 : Al1;
    const __nv_bfloat16* BhU = (set == 0) ? Bh0 : ((set == 1) ? Bh1 : Bh2);
    const __nv_bfloat16* BlU = (set == 0) ? Bl0 : ((set == 1) ? Bl1 : Bl2);
    const float* biasU = (set == 0) ? bias0 : ((set == 1) ? bias1 : bias2);
    float* CfU = (set == 0) ? Cf0 : ((set == 1) ? Cf1 : Cf2);
    __nv_bfloat16* ChU = (set == 0) ? Ch0 : ((set == 1) ? Ch1 : Ch2);
    __nv_bfloat16* ClU = (set == 0) ? Cl0 : ((set == 1) ? Cl1 : Cl2);
    const int reluU = (set == 0) ? relu0 : ((set == 1) ? relu1 : relu2);

    const __nv_bfloat16* Ahg = AhU + (size_t)m0 * 512;
    const __nv_bfloat16* Alg = AlU + (size_t)m0 * 512;
    const __nv_bfloat16* Bhg = BhU + (size_t)n0 * 512;
    const __nv_bfloat16* Blg = BlU + (size_t)n0 * 512;

    int frow[4], fc[4];
    uint32_t foff[4];
#pragma unroll
    for (int j = 0; j < 4; j++) {
        int lin = tid + j * 128;
        frow[j] = lin >> 2;
        fc[j]   = lin & 3;
        foff[j] = frow[j] * 64 + ((uint32_t)(fc[j] ^ ((frow[j] >> 1) & 3)) << 4);
    }

#define FILL(kc, st)                                                          \
    do {                                                                      \
        uint32_t s_ = sb + (st) * 32768;                                      \
        _Pragma("unroll")                                                     \
        for (int j = 0; j < 4; j++) {                                         \
            size_t g_ = (size_t)frow[j] * 512 + (kc) * 32 + fc[j] * 8;        \
            cp16(s_ + foff[j],          Ahg + g_);                            \
            cp16(s_ + 8192  + foff[j],  Alg + g_);                            \
            cp16(s_ + 16384 + foff[j],  Bhg + g_);                            \
            cp16(s_ + 24576 + foff[j],  Blg + g_);                            \
        }                                                                     \
        asm volatile("cp.async.commit_group;");                               \
    } while (0)

    float acc[4][8][4];
#pragma unroll
    for (int i = 0; i < 4; i++)
#pragma unroll
        for (int j = 0; j < 8; j++)
#pragma unroll
            for (int k = 0; k < 4; k++) acc[i][j][k] = 0.f;

    const int rA_base = wm * 64 + (lane & 7) + ((lane >> 3) & 1) * 8;
    const uint32_t kbA = ((lane >> 4) & 1) * 16;
    const int rB_base = wn * 64 + (lane & 7) + ((lane >> 4) & 1) * 8;
    const uint32_t kbB = ((lane >> 3) & 1) * 16;

    FILL(0, 0);
    FILL(1, 1);

    for (int c = 0; c < 16; c++) {
        if (c < 15) asm volatile("cp.async.wait_group 1;");
        else        asm volatile("cp.async.wait_group 0;");
        __syncthreads();

        const uint32_t st = (c & 1) * 32768;
        const uint32_t sAh = sb + st, sAl = sAh + 8192;
        const uint32_t sBh = sAh + 16384, sBl = sAh + 24576;

#pragma unroll
        for (int ks = 0; ks < 2; ks++) {
            uint32_t ah[4][4], al[4][4], bh[4][4], bl[4][4];
#pragma unroll
            for (int mt = 0; mt < 4; mt++) {
                int r = rA_base + mt * 16;
                uint32_t kb = kbA + ks * 32;
                uint32_t off = r * 64 + (kb ^ (((r >> 1) & 3) << 4));
                ldsm4(sAh + off, ah[mt]);
                ldsm4(sAl + off, al[mt]);
            }
#pragma unroll
            for (int p = 0; p < 4; p++) {
                int r = rB_base + p * 16;
                uint32_t kb = kbB + ks * 32;
                uint32_t off = r * 64 + (kb ^ (((r >> 1) & 3) << 4));
                ldsm4(sBh + off, bh[p]);
                ldsm4(sBl + off, bl[p]);
            }
            // pass 0: Ah * Bh  (32 independent MMAs)
#pragma unroll
            for (int mt = 0; mt < 4; mt++)
#pragma unroll
                for (int p = 0; p < 4; p++) {
                    mma_bf16(acc[mt][2 * p],     ah[mt], bh[p][0], bh[p][1]);
                    mma_bf16(acc[mt][2 * p + 1], ah[mt], bh[p][2], bh[p][3]);
                }
            // pass 1: Ah * Bl
#pragma unroll
            for (int mt = 0; mt < 4; mt++)
#pragma unroll
                for (int p = 0; p < 4; p++) {
                    mma_bf16(acc[mt][2 * p],     ah[mt], bl[p][0], bl[p][1]);
                    mma_bf16(acc[mt][2 * p + 1], ah[mt], bl[p][2], bl[p][3]);
                }
            // pass 2: Al * Bh
#pragma unroll
            for (int mt = 0; mt < 4; mt++)
#pragma unroll
                for (int p = 0; p < 4; p++) {
                    mma_bf16(acc[mt][2 * p],     al[mt], bh[p][0], bh[p][1]);
                    mma_bf16(acc[mt][2 * p + 1], al[mt], bh[p][2], bh[p][3]);
                }
        }
        __syncthreads();
        if (c + 2 < 16) FILL(c + 2, (c & 1));
    }

    // ---- epilogue ----
#pragma unroll
    for (int mt = 0; mt < 4; mt++) {
        int row = m0 + wm * 64 + mt * 16 + (lane >> 2);
#pragma unroll
        for (int nt = 0; nt < 8; nt++) {
            int col = n0 + wn * 64 + nt * 8 + (lane & 3) * 2;
            float2 bb = __ldg((const float2*)(biasU + col));
            float v0 = acc[mt][nt][0] + bb.x;
            float v1 = acc[mt][nt][1] + bb.y;
            float v2 = acc[mt][nt][2] + bb.x;
            float v3 = acc[mt][nt][3] + bb.y;
            if (reluU) {
                v0 = fmaxf(v0, 0.f); v1 = fmaxf(v1, 0.f);
                v2 = fmaxf(v2, 0.f); v3 = fmaxf(v3, 0.f);
            }
            if (CfU) {
                *(float2*)(CfU + (size_t)row * 512 + col)       = make_float2(v0, v1);
                *(float2*)(CfU + (size_t)(row + 8) * 512 + col) = make_float2(v2, v3);
            }
            if (ChU) {
                __nv_bfloat162 h0, l0, h1, l1;
                split2(v0, v1, h0, l0);
                split2(v2, v3, h1, l1);
                *(__nv_bfloat162*)(ChU + (size_t)row * 512 + col)       = h0;
                *(__nv_bfloat162*)(ClU + (size_t)row * 512 + col)       = l0;
                *(__nv_bfloat162*)(ChU + (size_t)(row + 8) * 512 + col) = h1;
                *(__nv_bfloat162*)(ClU + (size_t)(row + 8) * 512 + col) = l1;
            }
        }
    }
#undef FILL
}

// ---------------------------------------------------------------------------
// Tensor-core causal attention per (b,n,h): T=64, D=64. 128 threads, 4 warps.
// MMA passes reordered (hh/hl/lh per ks) to break accumulator RAW chains;
// per-accumulator FP order identical to R9 (bit-exact).
// Masked BEFORE scaling: masked logit = -32767/8.
// ---------------------------------------------------------------------------
__global__ __launch_bounds__(128)
void attn_mma(const __nv_bfloat16* __restrict__ qh, const __nv_bfloat16* __restrict__ ql,
              const __nv_bfloat16* __restrict__ kh, const __nv_bfloat16* __restrict__ kl,
              const __nv_bfloat16* __restrict__ vh, const __nv_bfloat16* __restrict__ vl,
              __nv_bfloat16* __restrict__ oh, __nv_bfloat16* __restrict__ ol)
{
    __shared__ __align__(128) unsigned char sm[6 * 8192];  // Qh Ql Kh Kl Vh Vl
    const uint32_t sb = smem_u32(sm);
    const uint32_t sQh = sb, sQl = sb + 8192;
    const uint32_t sKh = sb + 16384, sKl = sb + 24576;
    const uint32_t sVh = sb + 32768, sVl = sb + 40960;

    const int idx = blockIdx.x;
    const int h = idx & 7;
    const int n = (idx >> 3) & 255;
    const int b = idx >> 11;
    const size_t base = ((size_t)(b * T_) * N_ + n) * FEAT + h * D_;
    const int tid = threadIdx.x;
    const size_t tstride = (size_t)N_ * FEAT;

#define LOADM(ptr, moff)                                                      \
    _Pragma("unroll")                                                         \
    for (int i = 0; i < 4; i++) {                                             \
        int lin = tid + i * 128;                                              \
        int t_ = lin >> 3, q_ = lin & 7;                                      \
        cp16(sb + (moff) + t_ * 128 + ((q_ ^ (t_ & 7)) << 4),                 \
             (ptr) + base + (size_t)t_ * tstride + q_ * 8);                   \
    }
    LOADM(qh, 0);
    LOADM(ql, 8192);
    LOADM(kh, 16384);
    LOADM(kl, 24576);
    LOADM(vh, 32768);
    LOADM(vl, 40960);
#undef LOADM
    asm volatile("cp.async.commit_group;");
    asm volatile("cp.async.wait_group 0;");
    __syncthreads();

    const int w = tid >> 5;
    const int lane = tid & 31;
    const int m0 = w * 16;
    const float NEG8 = -4095.875f;

    // ---- QK^T ----
    uint32_t aqh[4][4], aql[4][4];
    {
        int r = m0 + (lane & 7) + ((lane >> 3) & 1) * 8;
        int qc = lane >> 4;
#pragma unroll
        for (int ks = 0; ks < 4; ks++) {
            uint32_t off = r * 128 + (((ks * 2 + qc) ^ (r & 7)) << 4);
            ldsm4(sQh + off, aqh[ks]);
            ldsm4(sQl + off, aql[ks]);
        }
    }

    float acc[8][4];
#pragma unroll
    for (int i = 0; i < 8; i++)
#pragma unroll
        for (int j = 0; j < 4; j++) acc[i][j] = 0.f;

    {
        int rn = (lane & 7) + ((lane >> 4) & 1) * 8;
        int kc = (lane >> 3) & 1;
#pragma unroll
        for (int ks = 0; ks < 4; ks++) {
            uint32_t bh[4][4], bl[4][4];
#pragma unroll
            for (int p = 0; p < 4; p++) {
                int rt = p * 16 + rn;
                uint32_t off = rt * 128 + (((ks * 2 + kc) ^ (rt & 7)) << 4);
                ldsm4(sKh + off, bh[p]);
                ldsm4(sKl + off, bl[p]);
            }
            // pass hh
#pragma unroll
            for (int p = 0; p < 4; p++) {
                mma_bf16(acc[2 * p],     aqh[ks], bh[p][0], bh[p][1]);
                mma_bf16(acc[2 * p + 1], aqh[ks], bh[p][2], bh[p][3]);
            }
            // pass hl
#pragma unroll
            for (int p = 0; p < 4; p++) {
                mma_bf16(acc[2 * p],     aqh[ks], bl[p][0], bl[p][1]);
                mma_bf16(acc[2 * p + 1], aqh[ks], bl[p][2], bl[p][3]);
            }
            // pass lh
#pragma unroll
            for (int p = 0; p < 4; p++) {
                mma_bf16(acc[2 * p],     aql[ks], bh[p][0], bh[p][1]);
                mma_bf16(acc[2 * p + 1], aql[ks], bh[p][2], bh[p][3]);
            }
        }
    }

    // ---- softmax (mask before scale) ----
    const int colb = (lane & 3) * 2;
    const int r0 = m0 + (lane >> 2), r1 = r0 + 8;
    float m0v = NEG8, m1v = NEG8;
#pragma unroll
    for (int nt = 0; nt < 8; nt++) {
        int c = nt * 8 + colb;
        acc[nt][0] = (c     <= r0) ? acc[nt][0] * 0.125f : NEG8;
        acc[nt][1] = (c + 1 <= r0) ? acc[nt][1] * 0.125f : NEG8;
        acc[nt][2] = (c     <= r1) ? acc[nt][2] * 0.125f : NEG8;
        acc[nt][3] = (c + 1 <= r1) ? acc[nt][3] * 0.125f : NEG8;
        m0v = fmaxf(m0v, fmaxf(acc[nt][0], acc[nt][1]));
        m1v = fmaxf(m1v, fmaxf(acc[nt][2], acc[nt][3]));
    }
    m0v = fmaxf(m0v, __shfl_xor_sync(0xffffffffu, m0v, 1));
    m0v = fmaxf(m0v, __shfl_xor_sync(0xffffffffu, m0v, 2));
    m1v = fmaxf(m1v, __shfl_xor_sync(0xffffffffu, m1v, 1));
    m1v = fmaxf(m1v, __shfl_xor_sync(0xffffffffu, m1v, 2));

    float sum0 = 0.f, sum1 = 0.f;
#pragma unroll
    for (int nt = 0; nt < 8; nt++) {
        acc[nt][0] = __expf(acc[nt][0] - m0v);
        acc[nt][1] = __expf(acc[nt][1] - m0v);
        acc[nt][2] = __expf(acc[nt][2] - m1v);
        acc[nt][3] = __expf(acc[nt][3] - m1v);
        sum0 += acc[nt][0] + acc[nt][1];
        sum1 += acc[nt][2] + acc[nt][3];
    }
    sum0 += __shfl_xor_sync(0xffffffffu, sum0, 1);
    sum0 += __shfl_xor_sync(0xffffffffu, sum0, 2);
    sum1 += __shfl_xor_sync(0xffffffffu, sum1, 1);
    sum1 += __shfl_xor_sync(0xffffffffu, sum1, 2);
    const float inv0 = 1.f / sum0, inv1 = 1.f / sum1;

    // ---- write P hi/lo into this warp's own Q smem rows ----
#pragma unroll
    for (int nt = 0; nt < 8; nt++) {
        __nv_bfloat162 hh, ll;
        split2(acc[nt][0] * inv0, acc[nt][1] * inv0, hh, ll);
        uint32_t o0 = r0 * 128 + ((nt ^ (r0 & 7)) << 4) + colb * 2;
        *(__nv_bfloat162*)(sm + o0)        = hh;
        *(__nv_bfloat162*)(sm + 8192 + o0) = ll;
        split2(acc[nt][2] * inv1, acc[nt][3] * inv1, hh, ll);
        uint32_t o1 = r1 * 128 + ((nt ^ (r1 & 7)) << 4) + colb * 2;
        *(__nv_bfloat162*)(sm + o1)        = hh;
        *(__nv_bfloat162*)(sm + 8192 + o1) = ll;
    }
    __syncwarp();

    // ---- O = P V ----
    float accO[8][4];
#pragma unroll
    for (int i = 0; i < 8; i++)
#pragma unroll
        for (int j = 0; j < 4; j++) accO[i][j] = 0.f;

    {
        int rp = m0 + (lane & 7) + ((lane >> 3) & 1) * 8;
        int pqc = lane >> 4;
        int sv = lane & 15;
        int vqc = lane >> 4;
#pragma unroll
        for (int ks = 0; ks < 4; ks++) {
            uint32_t offP = rp * 128 + (((ks * 2 + pqc) ^ (rp & 7)) << 4);
            uint32_t aph[4], apl[4];
            ldsm4(sQh + offP, aph);
            ldsm4(sQl + offP, apl);
            int rv = ks * 16 + sv;
            uint32_t bh[4][4], bl[4][4];
#pragma unroll
            for (int dt = 0; dt < 4; dt++) {
                uint32_t offV = rv * 128 + (((dt * 2 + vqc) ^ (rv & 7)) << 4);
                ldsm4t(sVh + offV, bh[dt]);
                ldsm4t(sVl + offV, bl[dt]);
            }
            // pass hh
#pragma unroll
            for (int dt = 0; dt < 4; dt++) {
                mma_bf16(accO[2 * dt],     aph, bh[dt][0], bh[dt][1]);
                mma_bf16(accO[2 * dt + 1], aph, bh[dt][2], bh[dt][3]);
            }
            // pass hl
#pragma unroll
            for (int dt = 0; dt < 4; dt++) {
                mma_bf16(accO[2 * dt],     aph, bl[dt][0], bl[dt][1]);
                mma_bf16(accO[2 * dt + 1], aph, bl[dt][2], bl[dt][3]);
            }
            // pass lh
#pragma unroll
            for (int dt = 0; dt < 4; dt++) {
                mma_bf16(accO[2 * dt],     apl, bh[dt][0], bh[dt][1]);
                mma_bf16(accO[2 * dt + 1], apl, bh[dt][2], bh[dt][3]);
            }
        }
    }

    // ---- store O hi/lo ----
#pragma unroll
    for (int nt = 0; nt < 8; nt++) {
        int col = nt * 8 + colb;
        __nv_bfloat162 hh, ll;
        split2(accO[nt][0], accO[nt][1], hh, ll);
        size_t o0 = base + (size_t)r0 * tstride + col;
        *(__nv_bfloat162*)(oh + o0) = hh;
        *(__nv_bfloat162*)(ol + o0) = ll;
        split2(accO[nt][2], accO[nt][3], hh, ll);
        size_t o1 = base + (size_t)r1 * tstride + col;
        *(__nv_bfloat162*)(oh + o1) = hh;
        *(__nv_bfloat162*)(ol + o1) = ll;
    }
}

// ---------------------------------------------------------------------------
// out = LayerNorm(a + (bh+bl)). Optional fp32 out, optional bf16 hi/lo out.
// ---------------------------------------------------------------------------
__global__ __launch_bounds__(256)
void add_ln(const float* __restrict__ a,
            const __nv_bfloat162* __restrict__ bh, const __nv_bfloat162* __restrict__ bl,
            float* __restrict__ out,
            __nv_bfloat162* __restrict__ oh, __nv_bfloat162* __restrict__ ol)
{
    int row = blockIdx.x * 8 + (threadIdx.x >> 5);
    int l = threadIdx.x & 31;
    const float4* pa = (const float4*)(a + (size_t)row * 512);

    float4 x[4];
    float s = 0.f;
#pragma unroll
    for (int i = 0; i < 4; i++) {
        float4 u = pa[l + i * 32];
        int fi = row * 128 + l + i * 32;
        __nv_bfloat162 h0 = bh[2 * fi], h1 = bh[2 * fi + 1];
        __nv_bfloat162 l0 = bl[2 * fi], l1 = bl[2 * fi + 1];
        float4 w = make_float4(__low2float(h0) + __low2float(l0),
                               __high2float(h0) + __high2float(l0),
                               __low2float(h1) + __low2float(l1),
                               __high2float(h1) + __high2float(l1));
        x[i] = make_float4(u.x + w.x, u.y + w.y, u.z + w.z, u.w + w.w);
        s += x[i].x + x[i].y + x[i].z + x[i].w;
    }
#pragma unroll
    for (int o = 16; o; o >>= 1) s += __shfl_xor_sync(0xffffffffu, s, o);
    float mean = s * (1.f / 512.f);

    float vs = 0.f;
#pragma unroll
    for (int i = 0; i < 4; i++) {
        float dx = x[i].x - mean, dy = x[i].y - mean, dz = x[i].z - mean, dw = x[i].w - mean;
        vs += dx * dx + dy * dy + dz * dz + dw * dw;
    }
#pragma unroll
    for (int o = 16; o; o >>= 1) vs += __shfl_xor_sync(0xffffffffu, vs, o);
    float invstd = rsqrtf(vs * (1.f / 512.f) + 1e-5f);

#pragma unroll
    for (int i = 0; i < 4; i++) {
        float y0 = (x[i].x - mean) * invstd, y1 = (x[i].y - mean) * invstd;
        float y2 = (x[i].z - mean) * invstd, y3 = (x[i].w - mean) * invstd;
        int fi = row * 128 + l + i * 32;
        if (out)
            ((float4*)(out + (size_t)row * 512))[l + i * 32] = make_float4(y0, y1, y2, y3);
        if (oh) {
            __nv_bfloat162 h0, l0, h1, l1;
            split2(y0, y1, h0, l0);
            split2(y2, y3, h1, l1);
            oh[2 * fi] = h0; oh[2 * fi + 1] = h1;
            ol[2 * fi] = l0; ol[2 * fi + 1] = l1;
        }
    }
}

// ---------------------------------------------------------------------------
// Launch pipeline (graph-capturable: launches only)
// ---------------------------------------------------------------------------
extern "C" void kernel_launch(void* const* d_in, const int* in_sizes, int n_in,
                              void* d_out, int out_size)
{
    const float* xl = (const float*)d_in[0];
    const float* xh = (const float*)d_in[1];
    const float* te = (const float*)d_in[2];
    const float* Wq = (const float*)d_in[3];
    const float* bq = (const float*)d_in[4];
    const float* Wk = (const float*)d_in[5];
    const float* bk = (const float*)d_in[6];
    const float* Wv = (const float*)d_in[7];
    const float* bv = (const float*)d_in[8];
    const float* Wo = (const float*)d_in[9];
    const float* bo = (const float*)d_in[10];
    const float* W1 = (const float*)d_in[11];
    const float* b1 = (const float*)d_in[12];
    const float* W2 = (const float*)d_in[13];
    const float* b2 = (const float*)d_in[14];
    float* out = (float*)d_out;

    float *s2, *s3;
    __nv_bfloat16 *bf, *wh, *wl;
    cudaGetSymbolAddress((void**)&s2, g_s2);
    cudaGetSymbolAddress((void**)&s3, g_s3);
    cudaGetSymbolAddress((void**)&bf, g_bf);
    cudaGetSymbolAddress((void**)&wh, g_wh);
    cudaGetSymbolAddress((void**)&wl, g_wl);

    __nv_bfloat16* s0h = bf + 0ull  * ELEMS;
    __nv_bfloat16* s0l = bf + 1ull  * ELEMS;
    __nv_bfloat16* s1h = bf + 2ull  * ELEMS;
    __nv_bfloat16* s1l = bf + 3ull  * ELEMS;
    __nv_bfloat16* qh  = bf + 4ull  * ELEMS;
    __nv_bfloat16* ql  = bf + 5ull  * ELEMS;
    __nv_bfloat16* kh  = bf + 6ull  * ELEMS;
    __nv_bfloat16* kl  = bf + 7ull  * ELEMS;
    __nv_bfloat16* vvh = bf + 8ull  * ELEMS;
    __nv_bfloat16* vvl = bf + 9ull  * ELEMS;
    __nv_bfloat16* aoh = bf + 10ull * ELEMS;
    __nv_bfloat16* aol = bf + 11ull * ELEMS;
    __nv_bfloat16* vah = bf + 12ull * ELEMS;
    __nv_bfloat16* val_ = bf + 13ull * ELEMS;
    __nv_bfloat16* f1h = bf + 14ull * ELEMS;
    __nv_bfloat16* f1l = bf + 15ull * ELEMS;

    cudaFuncSetAttribute(gemm_bf3, cudaFuncAttributeMaxDynamicSharedMemorySize, 65536);

    const dim3 gg(4, 1024);
    const dim3 gqkv(12, 1024);
    const int nadd = ELEMS / 4 / 256;

    // 0: weights transpose + split
    prep_w<<<dim3(16, 16, 6), dim3(32, 8)>>>(Wq, Wk, Wv, Wo, W1, W2, wh, wl);
    // 1: fused residual adds + splits
    add_te01<<<nadd, 256>>>((const float4*)xl, (const float4*)xh, (const float4*)te,
                            (__nv_bfloat162*)s0h, (__nv_bfloat162*)s0l,
                            (__nv_bfloat162*)s1h, (__nv_bfloat162*)s1l);
    // 2: fused Q+K+V projection -> bf16 hi/lo pairs
    gemm_bf3<<<gqkv, 128, 65536>>>(s0h, s0l, s1h, s1l,
                                   wh + 0 * WSZ, wl + 0 * WSZ, bq, 0, qh, ql, 0,
                                   wh + 1 * WSZ, wl + 1 * WSZ, bk, 0, kh, kl, 1,
                                   wh + 2 * WSZ, wl + 2 * WSZ, bv, 0, vvh, vvl, 1);
    // 3: tensor-core attention
    attn_mma<<<B_ * N_ * H_, 128>>>(qh, ql, kh, kl, vvh, vvl, aoh, aol);
    // 4: Wo projection -> s3 fp32
    gemm_bf3<<<gg, 128, 65536>>>(aoh, aol, 0, 0,
                                 wh + 3 * WSZ, wl + 3 * WSZ, bo, s3, 0, 0, 0,
                                 0, 0, 0, 0, 0, 0, 0,
                                 0, 0, 0, 0, 0, 0, 0);
    // 5: val = LN(o + (s0h+s0l)) -> vah/val_ (bf16 only)
    add_ln<<<TOKENS / 8, 256>>>(s3, (const __nv_bfloat162*)s0h,
                                (const __nv_bfloat162*)s0l, 0,
                                (__nv_bfloat162*)vah, (__nv_bfloat162*)val_);
    // 6: ff1 = relu(val @ W1 + b1) -> f1h/f1l
    gemm_bf3<<<gg, 128, 65536>>>(vah, val_, 0, 0,
                                 wh + 4 * WSZ, wl + 4 * WSZ, b1, 0, f1h, f1l, 1,
                                 0, 0, 0, 0, 0, 0, 0,
                                 0, 0, 0, 0, 0, 0, 0);
    // 7: ff2 = ff1 @ W2 + b2 -> s2 fp32
    gemm_bf3<<<gg, 128, 65536>>>(f1h, f1l, 0, 0,
                                 wh + 5 * WSZ, wl + 5 * WSZ, b2, s2, 0, 0, 0,
                                 0, 0, 0, 0, 0, 0, 0,
                                 0, 0, 0, 0, 0, 0, 0);
    // 8: out = LN(ff2 + (vah+val_))
    add_ln<<<TOKENS / 8, 256>>>(s2, (const __nv_bfloat162*)vah,
                                (const __nv_bfloat162*)val_, out, 0, 0);
}

// round 11
// speedup vs baseline: 2.6179x; 2.1309x over previous
#include <cuda_runtime.h>
#include <cuda_fp16.h>
#include <math.h>
#include <stdint.h>

#define B_ 8
#define T_ 64
#define N_ 256
#define H_ 8
#define D_ 64
#define FEAT 512
#define TOKENS (B_*T_*N_)          /* 131072 */
#define ELEMS  (TOKENS*FEAT)       /* 67108864 */
#define WSZ    (512*512)

// ---------------------------------------------------------------------------
// Scratch (device globals — no cudaMalloc allowed)
// ---------------------------------------------------------------------------
__device__ float g_s2[ELEMS];        // ff2 out (fp32)
__device__ float g_s3[ELEMS];        // Wo out (fp32)
__device__ __half g_hf[8ull * ELEMS]; // s0 s1 q k v ao va f1
__device__ __half g_wt[6 * WSZ];      // K-major fp16 weights

// ---------------------------------------------------------------------------
// Helpers
// ---------------------------------------------------------------------------
__device__ __forceinline__ uint32_t smem_u32(const void* p) {
    uint32_t a;
    asm("{ .reg .u64 t; cvta.to.shared.u64 t, %1; cvt.u32.u64 %0, t; }" : "=r"(a) : "l"(p));
    return a;
}

__device__ __forceinline__ void cp16(uint32_t dst, const void* src) {
    asm volatile("cp.async.cg.shared.global [%0], [%1], 16;"
                 :: "r"(dst), "l"(__cvta_generic_to_global(src)));
}

__device__ __forceinline__ void ldsm4(uint32_t addr, uint32_t* r) {
    asm volatile("ldmatrix.sync.aligned.m8n8.x4.shared.b16 {%0,%1,%2,%3}, [%4];"
                 : "=r"(r[0]), "=r"(r[1]), "=r"(r[2]), "=r"(r[3]) : "r"(addr));
}

__device__ __forceinline__ void ldsm4t(uint32_t addr, uint32_t* r) {
    asm volatile("ldmatrix.sync.aligned.m8n8.x4.trans.shared.b16 {%0,%1,%2,%3}, [%4];"
                 : "=r"(r[0]), "=r"(r[1]), "=r"(r[2]), "=r"(r[3]) : "r"(addr));
}

__device__ __forceinline__ void mma_fp16(float* d, const uint32_t* a,
                                         uint32_t b0, uint32_t b1) {
    asm volatile(
        "mma.sync.aligned.m16n8k16.row.col.f32.f16.f16.f32 "
        "{%0,%1,%2,%3}, {%4,%5,%6,%7}, {%8,%9}, {%0,%1,%2,%3};"
        : "+f"(d[0]), "+f"(d[1]), "+f"(d[2]), "+f"(d[3])
        : "r"(a[0]), "r"(a[1]), "r"(a[2]), "r"(a[3]), "r"(b0), "r"(b1));
}

// ---------------------------------------------------------------------------
// Weight prep: transpose to K-major fp16. Wt[z][n][k] = fp16(W_z[k][n]).
// ---------------------------------------------------------------------------
__global__ __launch_bounds__(256)
void prep_w(const float* W0, const float* W1, const float* W2,
            const float* W3, const float* W4, const float* W5,
            __half* __restrict__ Wt)
{
    const float* Ws[6] = {W0, W1, W2, W3, W4, W5};
    const float* W = Ws[blockIdx.z];
    __shared__ float t[32][33];
    int bx = blockIdx.x * 32, by = blockIdx.y * 32;
#pragma unroll
    for (int r = 0; r < 32; r += 8)
        t[threadIdx.y + r][threadIdx.x] =
            W[(size_t)(by + threadIdx.y + r) * 512 + bx + threadIdx.x];
    __syncthreads();
    size_t base = (size_t)blockIdx.z * WSZ;
#pragma unroll
    for (int r = 0; r < 32; r += 8)
        Wt[base + (size_t)(bx + threadIdx.y + r) * 512 + by + threadIdx.x] =
            __float2half_rn(t[threadIdx.x][threadIdx.y + r]);
}

// ---------------------------------------------------------------------------
// Fused residual adds: s0 = fp16(xl+te), s1 = fp16(xh+te).
// ---------------------------------------------------------------------------
__global__ __launch_bounds__(256)
void add_te01(const float4* __restrict__ xl, const float4* __restrict__ xh,
              const float4* __restrict__ te,
              __half2* __restrict__ o0, __half2* __restrict__ o1)
{
    int i = blockIdx.x * 256 + threadIdx.x;
    float4 t = te[i];
    float4 a = xl[i];
    float4 b = xh[i];
    o0[2 * i]     = __floats2half2_rn(a.x + t.x, a.y + t.y);
    o0[2 * i + 1] = __floats2half2_rn(a.z + t.z, a.w + t.w);
    o1[2 * i]     = __floats2half2_rn(b.x + t.x, b.y + t.y);
    o1[2 * i + 1] = __floats2half2_rn(b.z + t.z, b.w + t.w);
}

// ---------------------------------------------------------------------------
// FP16 tensor-core GEMM (single pass), 2-stage cp.async. CTA 128x128,
// 128 thr, 4 warps (64x64 warp tiles). Triple operand set via blockIdx.x>>2
// (fused Q+K+V). Per set: optional fp32 out and/or fp16 out, optional relu.
// smem/stage: A 8KB + B 8KB = 16KB; 2 stages = 32KB dynamic.
// ---------------------------------------------------------------------------
__global__ __launch_bounds__(128, 2)
void gemm_fp16(const __half* __restrict__ A0, const __half* __restrict__ A1,
               const __half* B0, const float* bias0, float* Cf0, __half* Ch0, int relu0,
               const __half* B1, const float* bias1, float* Cf1, __half* Ch1, int relu1,
               const __half* B2, const float* bias2, float* Cf2, __half* Ch2, int relu2)
{
    extern __shared__ __align__(128) unsigned char smem[];
    const uint32_t sb = smem_u32(smem);

    const int tid  = threadIdx.x;
    const int lane = tid & 31;
    const int warp = tid >> 5;
    const int wm = warp >> 1, wn = warp & 1;
    const int m0 = blockIdx.y * 128;

    const int set = blockIdx.x >> 2;
    const int n0  = (blockIdx.x & 3) * 128;

    const __half* AU = (set == 0) ? A0 : A1;
    const __half* BU = (set == 0) ? B0 : ((set == 1) ? B1 : B2);
    const float* biasU = (set == 0) ? bias0 : ((set == 1) ? bias1 : bias2);
    float* CfU = (set == 0) ? Cf0 : ((set == 1) ? Cf1 : Cf2);
    __half* ChU = (set == 0) ? Ch0 : ((set == 1) ? Ch1 : Ch2);
    const int reluU = (set == 0) ? relu0 : ((set == 1) ? relu1 : relu2);

    const __half* Ag = AU + (size_t)m0 * 512;
    const __half* Bg = BU + (size_t)n0 * 512;

    int frow[4], fc[4];
    uint32_t foff[4];
#pragma unroll
    for (int j = 0; j < 4; j++) {
        int lin = tid + j * 128;
        frow[j] = lin >> 2;
        fc[j]   = lin & 3;
        foff[j] = frow[j] * 64 + ((uint32_t)(fc[j] ^ ((frow[j] >> 1) & 3)) << 4);
    }

#define FILL(kc, st)                                                          \
    do {                                                                      \
        uint32_t s_ = sb + (st) * 16384;                                      \
        _Pragma("unroll")                                                     \
        for (int j = 0; j < 4; j++) {                                         \
            size_t g_ = (size_t)frow[j] * 512 + (kc) * 32 + fc[j] * 8;        \
            cp16(s_ + foff[j],         Ag + g_);                              \
            cp16(s_ + 8192 + foff[j],  Bg + g_);                              \
        }                                                                     \
        asm volatile("cp.async.commit_group;");                               \
    } while (0)

    float acc[4][8][4];
#pragma unroll
    for (int i = 0; i < 4; i++)
#pragma unroll
        for (int j = 0; j < 8; j++)
#pragma unroll
            for (int k = 0; k < 4; k++) acc[i][j][k] = 0.f;

    const int rA_base = wm * 64 + (lane & 7) + ((lane >> 3) & 1) * 8;
    const uint32_t kbA = ((lane >> 4) & 1) * 16;
    const int rB_base = wn * 64 + (lane & 7) + ((lane >> 4) & 1) * 8;
    const uint32_t kbB = ((lane >> 3) & 1) * 16;

    FILL(0, 0);
    FILL(1, 1);

    for (int c = 0; c < 16; c++) {
        if (c < 15) asm volatile("cp.async.wait_group 1;");
        else        asm volatile("cp.async.wait_group 0;");
        __syncthreads();

        const uint32_t sA = sb + (c & 1) * 16384;
        const uint32_t sB = sA + 8192;

#pragma unroll
        for (int ks = 0; ks < 2; ks++) {
            uint32_t ah[4][4], bh[4][4];
#pragma unroll
            for (int mt = 0; mt < 4; mt++) {
                int r = rA_base + mt * 16;
                uint32_t kb = kbA + ks * 32;
                ldsm4(sA + r * 64 + (kb ^ (((r >> 1) & 3) << 4)), ah[mt]);
            }
#pragma unroll
            for (int p = 0; p < 4; p++) {
                int r = rB_base + p * 16;
                uint32_t kb = kbB + ks * 32;
                ldsm4(sB + r * 64 + (kb ^ (((r >> 1) & 3) << 4)), bh[p]);
            }
#pragma unroll
            for (int mt = 0; mt < 4; mt++)
#pragma unroll
                for (int p = 0; p < 4; p++) {
                    mma_fp16(acc[mt][2 * p],     ah[mt], bh[p][0], bh[p][1]);
                    mma_fp16(acc[mt][2 * p + 1], ah[mt], bh[p][2], bh[p][3]);
                }
        }
        __syncthreads();
        if (c + 2 < 16) FILL(c + 2, (c & 1));
    }

    // ---- epilogue ----
#pragma unroll
    for (int mt = 0; mt < 4; mt++) {
        int row = m0 + wm * 64 + mt * 16 + (lane >> 2);
#pragma unroll
        for (int nt = 0; nt < 8; nt++) {
            int col = n0 + wn * 64 + nt * 8 + (lane & 3) * 2;
            float2 bb = __ldg((const float2*)(biasU + col));
            float v0 = acc[mt][nt][0] + bb.x;
            float v1 = acc[mt][nt][1] + bb.y;
            float v2 = acc[mt][nt][2] + bb.x;
            float v3 = acc[mt][nt][3] + bb.y;
            if (reluU) {
                v0 = fmaxf(v0, 0.f); v1 = fmaxf(v1, 0.f);
                v2 = fmaxf(v2, 0.f); v3 = fmaxf(v3, 0.f);
            }
            if (CfU) {
                *(float2*)(CfU + (size_t)row * 512 + col)       = make_float2(v0, v1);
                *(float2*)(CfU + (size_t)(row + 8) * 512 + col) = make_float2(v2, v3);
            }
            if (ChU) {
                *(__half2*)(ChU + (size_t)row * 512 + col)       = __floats2half2_rn(v0, v1);
                *(__half2*)(ChU + (size_t)(row + 8) * 512 + col) = __floats2half2_rn(v2, v3);
            }
        }
    }
#undef FILL
}

// ---------------------------------------------------------------------------
// FP16 tensor-core causal attention per (b,n,h): T=64, D=64. 128 thr, 4 warps.
// Warp w owns rows 16w..16w+15. Single-pass fp16 MMAs; fp32 softmax in
// fragments; P (fp16) overwrites warp-own Q smem rows; V via ldmatrix.trans.
// Masked BEFORE scaling: masked logit = -32767/8.
// smem: Q 8KB | K 8KB | V 8KB; rows 128B, chunk swizzle q^(row&7).
// ---------------------------------------------------------------------------
__global__ __launch_bounds__(128)
void attn_fp16(const __half* __restrict__ qf, const __half* __restrict__ kf,
               const __half* __restrict__ vf, __half* __restrict__ of)
{
    __shared__ __align__(128) unsigned char sm[3 * 8192];
    const uint32_t sb = smem_u32(sm);
    const uint32_t sQ = sb, sK = sb + 8192, sV = sb + 16384;

    const int idx = blockIdx.x;
    const int h = idx & 7;
    const int n = (idx >> 3) & 255;
    const int b = idx >> 11;
    const size_t base = ((size_t)(b * T_) * N_ + n) * FEAT + h * D_;
    const int tid = threadIdx.x;
    const size_t tstride = (size_t)N_ * FEAT;

#define LOADM(ptr, moff)                                                      \
    _Pragma("unroll")                                                         \
    for (int i = 0; i < 4; i++) {                                             \
        int lin = tid + i * 128;                                              \
        int t_ = lin >> 3, q_ = lin & 7;                                      \
        cp16(sb + (moff) + t_ * 128 + ((q_ ^ (t_ & 7)) << 4),                 \
             (ptr) + base + (size_t)t_ * tstride + q_ * 8);                   \
    }
    LOADM(qf, 0);
    LOADM(kf, 8192);
    LOADM(vf, 16384);
#undef LOADM
    asm volatile("cp.async.commit_group;");
    asm volatile("cp.async.wait_group 0;");
    __syncthreads();

    const int w = tid >> 5;
    const int lane = tid & 31;
    const int m0 = w * 16;
    const float NEG8 = -4095.875f;

    // ---- QK^T ----
    uint32_t aq[4][4];
    {
        int r = m0 + (lane & 7) + ((lane >> 3) & 1) * 8;
        int qc = lane >> 4;
#pragma unroll
        for (int ks = 0; ks < 4; ks++)
            ldsm4(sQ + r * 128 + (((ks * 2 + qc) ^ (r & 7)) << 4), aq[ks]);
    }

    float acc[8][4];
#pragma unroll
    for (int i = 0; i < 8; i++)
#pragma unroll
        for (int j = 0; j < 4; j++) acc[i][j] = 0.f;

    {
        int rn = (lane & 7) + ((lane >> 4) & 1) * 8;
        int kc = (lane >> 3) & 1;
#pragma unroll
        for (int ks = 0; ks < 4; ks++) {
#pragma unroll
            for (int p = 0; p < 4; p++) {
                int rt = p * 16 + rn;
                uint32_t bk[4];
                ldsm4(sK + rt * 128 + (((ks * 2 + kc) ^ (rt & 7)) << 4), bk);
                mma_fp16(acc[2 * p],     aq[ks], bk[0], bk[1]);
                mma_fp16(acc[2 * p + 1], aq[ks], bk[2], bk[3]);
            }
        }
    }

    // ---- softmax (mask before scale) ----
    const int colb = (lane & 3) * 2;
    const int r0 = m0 + (lane >> 2), r1 = r0 + 8;
    float m0v = NEG8, m1v = NEG8;
#pragma unroll
    for (int nt = 0; nt < 8; nt++) {
        int c = nt * 8 + colb;
        acc[nt][0] = (c     <= r0) ? acc[nt][0] * 0.125f : NEG8;
        acc[nt][1] = (c + 1 <= r0) ? acc[nt][1] * 0.125f : NEG8;
        acc[nt][2] = (c     <= r1) ? acc[nt][2] * 0.125f : NEG8;
        acc[nt][3] = (c + 1 <= r1) ? acc[nt][3] * 0.125f : NEG8;
        m0v = fmaxf(m0v, fmaxf(acc[nt][0], acc[nt][1]));
        m1v = fmaxf(m1v, fmaxf(acc[nt][2], acc[nt][3]));
    }
    m0v = fmaxf(m0v, __shfl_xor_sync(0xffffffffu, m0v, 1));
    m0v = fmaxf(m0v, __shfl_xor_sync(0xffffffffu, m0v, 2));
    m1v = fmaxf(m1v, __shfl_xor_sync(0xffffffffu, m1v, 1));
    m1v = fmaxf(m1v, __shfl_xor_sync(0xffffffffu, m1v, 2));

    float sum0 = 0.f, sum1 = 0.f;
#pragma unroll
    for (int nt = 0; nt < 8; nt++) {
        acc[nt][0] = __expf(acc[nt][0] - m0v);
        acc[nt][1] = __expf(acc[nt][1] - m0v);
        acc[nt][2] = __expf(acc[nt][2] - m1v);
        acc[nt][3] = __expf(acc[nt][3] - m1v);
        sum0 += acc[nt][0] + acc[nt][1];
        sum1 += acc[nt][2] + acc[nt][3];
    }
    sum0 += __shfl_xor_sync(0xffffffffu, sum0, 1);
    sum0 += __shfl_xor_sync(0xffffffffu, sum0, 2);
    sum1 += __shfl_xor_sync(0xffffffffu, sum1, 1);
    sum1 += __shfl_xor_sync(0xffffffffu, sum1, 2);
    const float inv0 = 1.f / sum0, inv1 = 1.f / sum1;

    // ---- write P (fp16) into this warp's own Q smem rows ----
#pragma unroll
    for (int nt = 0; nt < 8; nt++) {
        uint32_t o0 = r0 * 128 + ((nt ^ (r0 & 7)) << 4) + colb * 2;
        uint32_t o1 = r1 * 128 + ((nt ^ (r1 & 7)) << 4) + colb * 2;
        *(__half2*)(sm + o0) = __floats2half2_rn(acc[nt][0] * inv0, acc[nt][1] * inv0);
        *(__half2*)(sm + o1) = __floats2half2_rn(acc[nt][2] * inv1, acc[nt][3] * inv1);
    }
    __syncwarp();

    // ---- O = P V ----
    float accO[8][4];
#pragma unroll
    for (int i = 0; i < 8; i++)
#pragma unroll
        for (int j = 0; j < 4; j++) accO[i][j] = 0.f;

    {
        int rp = m0 + (lane & 7) + ((lane >> 3) & 1) * 8;
        int pqc = lane >> 4;
        int sv = lane & 15;
        int vqc = lane >> 4;
#pragma unroll
        for (int ks = 0; ks < 4; ks++) {
            uint32_t ap[4];
            ldsm4(sQ + rp * 128 + (((ks * 2 + pqc) ^ (rp & 7)) << 4), ap);
            int rv = ks * 16 + sv;
#pragma unroll
            for (int dt = 0; dt < 4; dt++) {
                uint32_t bv[4];
                ldsm4t(sV + rv * 128 + (((dt * 2 + vqc) ^ (rv & 7)) << 4), bv);
                mma_fp16(accO[2 * dt],     ap, bv[0], bv[1]);
                mma_fp16(accO[2 * dt + 1], ap, bv[2], bv[3]);
            }
        }
    }

    // ---- store O fp16 ----
#pragma unroll
    for (int nt = 0; nt < 8; nt++) {
        int col = nt * 8 + colb;
        *(__half2*)(of + base + (size_t)r0 * tstride + col) =
            __floats2half2_rn(accO[nt][0], accO[nt][1]);
        *(__half2*)(of + base + (size_t)r1 * tstride + col) =
            __floats2half2_rn(accO[nt][2], accO[nt][3]);
    }
}

// ---------------------------------------------------------------------------
// out = LayerNorm(a + b(fp16)). Optional fp32 out, optional fp16 out.
// One warp per 512-dim row.
// ---------------------------------------------------------------------------
__global__ __launch_bounds__(256)
void add_ln(const float* __restrict__ a, const __half2* __restrict__ b,
            float* __restrict__ out, __half2* __restrict__ oh)
{
    int row = blockIdx.x * 8 + (threadIdx.x >> 5);
    int l = threadIdx.x & 31;
    const float4* pa = (const float4*)(a + (size_t)row * 512);

    float4 x[4];
    float s = 0.f;
#pragma unroll
    for (int i = 0; i < 4; i++) {
        float4 u = pa[l + i * 32];
        int fi = row * 128 + l + i * 32;
        __half2 p0 = b[2 * fi], p1 = b[2 * fi + 1];
        x[i] = make_float4(u.x + __low2float(p0), u.y + __high2float(p0),
                           u.z + __low2float(p1), u.w + __high2float(p1));
        s += x[i].x + x[i].y + x[i].z + x[i].w;
    }
#pragma unroll
    for (int o = 16; o; o >>= 1) s += __shfl_xor_sync(0xffffffffu, s, o);
    float mean = s * (1.f / 512.f);

    float vs = 0.f;
#pragma unroll
    for (int i = 0; i < 4; i++) {
        float dx = x[i].x - mean, dy = x[i].y - mean, dz = x[i].z - mean, dw = x[i].w - mean;
        vs += dx * dx + dy * dy + dz * dz + dw * dw;
    }
#pragma unroll
    for (int o = 16; o; o >>= 1) vs += __shfl_xor_sync(0xffffffffu, vs, o);
    float invstd = rsqrtf(vs * (1.f / 512.f) + 1e-5f);

#pragma unroll
    for (int i = 0; i < 4; i++) {
        float y0 = (x[i].x - mean) * invstd, y1 = (x[i].y - mean) * invstd;
        float y2 = (x[i].z - mean) * invstd, y3 = (x[i].w - mean) * invstd;
        int fi = row * 128 + l + i * 32;
        if (out)
            ((float4*)(out + (size_t)row * 512))[l + i * 32] = make_float4(y0, y1, y2, y3);
        if (oh) {
            oh[2 * fi]     = __floats2half2_rn(y0, y1);
            oh[2 * fi + 1] = __floats2half2_rn(y2, y3);
        }
    }
}

// ---------------------------------------------------------------------------
// Launch pipeline (graph-capturable: launches only)
// ---------------------------------------------------------------------------
extern "C" void kernel_launch(void* const* d_in, const int* in_sizes, int n_in,
                              void* d_out, int out_size)
{
    const float* xl = (const float*)d_in[0];
    const float* xh = (const float*)d_in[1];
    const float* te = (const float*)d_in[2];
    const float* Wq = (const float*)d_in[3];
    const float* bq = (const float*)d_in[4];
    const float* Wk = (const float*)d_in[5];
    const float* bk = (const float*)d_in[6];
    const float* Wv = (const float*)d_in[7];
    const float* bv = (const float*)d_in[8];
    const float* Wo = (const float*)d_in[9];
    const float* bo = (const float*)d_in[10];
    const float* W1 = (const float*)d_in[11];
    const float* b1 = (const float*)d_in[12];
    const float* W2 = (const float*)d_in[13];
    const float* b2 = (const float*)d_in[14];
    float* out = (float*)d_out;

    float *s2, *s3;
    __half *hf, *wt;
    cudaGetSymbolAddress((void**)&s2, g_s2);
    cudaGetSymbolAddress((void**)&s3, g_s3);
    cudaGetSymbolAddress((void**)&hf, g_hf);
    cudaGetSymbolAddress((void**)&wt, g_wt);

    __half* s0f = hf + 0ull * ELEMS;
    __half* s1f = hf + 1ull * ELEMS;
    __half* qf  = hf + 2ull * ELEMS;
    __half* kf  = hf + 3ull * ELEMS;
    __half* vf  = hf + 4ull * ELEMS;
    __half* aof = hf + 5ull * ELEMS;
    __half* vaf = hf + 6ull * ELEMS;
    __half* f1f = hf + 7ull * ELEMS;

    cudaFuncSetAttribute(gemm_fp16, cudaFuncAttributeMaxDynamicSharedMemorySize, 32768);

    const dim3 gg(4, 1024);
    const dim3 gqkv(12, 1024);
    const int nadd = ELEMS / 4 / 256;

    // 0: weight transpose (fp16 K-major)
    prep_w<<<dim3(16, 16, 6), dim3(32, 8)>>>(Wq, Wk, Wv, Wo, W1, W2, wt);
    // 1: fused residual adds -> fp16
    add_te01<<<nadd, 256>>>((const float4*)xl, (const float4*)xh, (const float4*)te,
                            (__half2*)s0f, (__half2*)s1f);
    // 2: fused Q+K+V projection -> fp16
    gemm_fp16<<<gqkv, 128, 32768>>>(s0f, s1f,
                                    wt + 0 * WSZ, bq, 0, qf, 0,
                                    wt + 1 * WSZ, bk, 0, kf, 1,
                                    wt + 2 * WSZ, bv, 0, vf, 1);
    // 3: tensor-core attention -> fp16
    attn_fp16<<<B_ * N_ * H_, 128>>>(qf, kf, vf, aof);
    // 4: Wo projection -> s3 fp32
    gemm_fp16<<<gg, 128, 32768>>>(aof, 0,
                                  wt + 3 * WSZ, bo, s3, 0, 0,
                                  0, 0, 0, 0, 0,
                                  0, 0, 0, 0, 0);
    // 5: val = LN(o + s0f) -> vaf fp16
    add_ln<<<TOKENS / 8, 256>>>(s3, (const __half2*)s0f, 0, (__half2*)vaf);
    // 6: ff1 = relu(val @ W1 + b1) -> f1f fp16
    gemm_fp16<<<gg, 128, 32768>>>(vaf, 0,
                                  wt + 4 * WSZ, b1, 0, f1f, 1,
                                  0, 0, 0, 0, 0,
                                  0, 0, 0, 0, 0);
    // 7: ff2 = ff1 @ W2 + b2 -> s2 fp32
    gemm_fp16<<<gg, 128, 32768>>>(f1f, 0,
                                  wt + 5 * WSZ, b2, s2, 0, 0,
                                  0, 0, 0, 0, 0,
                                  0, 0, 0, 0, 0);
    // 8: out = LN(ff2 + vaf) -> fp32
    add_ln<<<TOKENS / 8, 256>>>(s2, (const __half2*)vaf, out, 0);
}